// round 9
// baseline (speedup 1.0000x reference)
#include <cuda_runtime.h>
#include <cuda_bf16.h>
#include <math.h>
#include <stdint.h>

namespace {

constexpr int B_ = 32;
constexpr int N_ = 64;
constexpr int C_ = 128;
constexpr int M_ = 15;
constexpr int E_ = B_ * N_ * N_;   // 131072
constexpr float LN_EPS = 1e-5f;
constexpr int TSTR = 136;          // padded bf16 row stride (272B: conflict-free ldmatrix)
constexpr int WSEG = 128 * TSTR;   // elements per weight segment

// ---------------- device scratch --------------------------------------------
__device__ __align__(16) __nv_bfloat16 g_t1h[(size_t)E_ * C_];
__device__ __align__(16) __nv_bfloat16 g_t1l[(size_t)E_ * C_];
__device__ __align__(16) float g_row [B_ * N_ * C_];
__device__ __align__(16) float g_colsum[B_ * N_ * C_];   // RAW sums (scaled on load)
__device__ __align__(16) float g_diag[B_ * N_ * C_];
__device__ __align__(16) float g_A [B_ * N_ * C_];
__device__ __align__(16) float g_Bv[B_ * N_ * C_];
__device__ __align__(16) float g_D [B_ * N_ * C_];
__device__ __align__(16) float g_Cc[B_ * C_];
__device__ __align__(16) float g_Ec[B_ * C_];
__device__ __align__(16) float g_WT[M_ * C_ * C_];          // [m][c][o]
__device__ __align__(16) __nv_bfloat16 g_Wb[4 * WSEG];      // {W0hi,W0lo,W1hi,W1lo}

// ---------------- helpers ----------------------------------------------------
__device__ __forceinline__ float gelu_exact(float v) {
    return 0.5f * v * (1.0f + erff(v * 0.70710678118654752440f));
}
__device__ __forceinline__ uint32_t smem_to_u32(const void* p) {
    uint32_t a;
    asm("{ .reg .u64 t; cvta.to.shared.u64 t, %1; cvt.u32.u64 %0, t; }" : "=r"(a) : "l"(p));
    return a;
}
__device__ __forceinline__ void ldsm4(uint32_t* r, uint32_t addr) {
    asm volatile("ldmatrix.sync.aligned.m8n8.x4.shared.b16 {%0,%1,%2,%3}, [%4];"
                 : "=r"(r[0]), "=r"(r[1]), "=r"(r[2]), "=r"(r[3]) : "r"(addr));
}
__device__ __forceinline__ void mma16816(float* d, const uint32_t* a,
                                         uint32_t b0, uint32_t b1) {
    asm volatile("mma.sync.aligned.m16n8k16.row.col.f32.bf16.bf16.f32 "
                 "{%0,%1,%2,%3}, {%4,%5,%6,%7}, {%8,%9}, {%0,%1,%2,%3};"
                 : "+f"(d[0]), "+f"(d[1]), "+f"(d[2]), "+f"(d[3])
                 : "r"(a[0]), "r"(a[1]), "r"(a[2]), "r"(a[3]), "r"(b0), "r"(b1));
}
__device__ __forceinline__ void cvt_split4(float4 v, uint2& h, uint2& l) {
    __nv_bfloat162 h0 = __floats2bfloat162_rn(v.x, v.y);
    __nv_bfloat162 h1 = __floats2bfloat162_rn(v.z, v.w);
    float r0 = v.x - __bfloat162float(h0.x);
    float r1 = v.y - __bfloat162float(h0.y);
    float r2 = v.z - __bfloat162float(h1.x);
    float r3 = v.w - __bfloat162float(h1.y);
    __nv_bfloat162 l0 = __floats2bfloat162_rn(r0, r1);
    __nv_bfloat162 l1 = __floats2bfloat162_rn(r2, r3);
    h.x = *reinterpret_cast<uint32_t*>(&h0); h.y = *reinterpret_cast<uint32_t*>(&h1);
    l.x = *reinterpret_cast<uint32_t*>(&l0); l.y = *reinterpret_cast<uint32_t*>(&l1);
}
__device__ __forceinline__ uint32_t split_pack(float a, float b, uint32_t& lo) {
    __nv_bfloat162 h = __floats2bfloat162_rn(a, b);
    float r0 = a - __bfloat162float(h.x);
    float r1 = b - __bfloat162float(h.y);
    __nv_bfloat162 l = __floats2bfloat162_rn(r0, r1);
    lo = *reinterpret_cast<uint32_t*>(&l);
    return *reinterpret_cast<uint32_t*>(&h);
}

#define CP_ASYNC16(dst, src) \
    asm volatile("cp.async.cg.shared.global [%0], [%1], 16;" :: "r"(dst), "l"(src))
#define CP_COMMIT() asm volatile("cp.async.commit_group;" ::: "memory")
#define CP_WAIT0()  asm volatile("cp.async.wait_group 0;" ::: "memory")

// ---------------- K0: coeffs + zero g_colsum --------------------------------
__global__ void __launch_bounds__(512) k_mix(
        const float* __restrict__ c00, const float* __restrict__ c01,
        const float* __restrict__ c10, const float* __restrict__ c11) {
    const int bx = blockIdx.x, tid = threadIdx.x;
    if (bx < 120) {
#pragma unroll
        for (int u = 0; u < 4; u++) {
            int idx = bx * 2048 + u * 512 + tid;
            int o = idx & 127, c = (idx >> 7) & 127, m = idx >> 14;
            float v = c00[o * M_ + m] * c10[o * C_ + c] + c01[c * M_ + m] * c11[o * C_ + c];
            g_WT[idx] = v;
            if (m < 2) {
                __nv_bfloat16 hb = __float2bfloat16_rn(v);
                float rr = v - __bfloat162float(hb);
                __nv_bfloat16 lo = __float2bfloat16_rn(rr);
                g_Wb[(m * 2 + 0) * WSEG + o * TSTR + c] = hb;
                g_Wb[(m * 2 + 1) * WSEG + o * TSTR + c] = lo;
            }
        }
    } else {   // zero col accumulators (device globals persist across replays)
        int base = (bx - 120) * 2048;
#pragma unroll
        for (int u = 0; u < 4; u++) g_colsum[base + u * 512 + tid] = 0.f;
    }
}

// ---------------- K1: warp-MMA input GEMM + GELU + LN + row/col/diag --------
constexpr int KI_WH = 0;
constexpr int KI_WL = 34816;
constexpr int KI_XH = 69632;
constexpr int KI_XL = 87040;
constexpr int KI_BI = 104448;
constexpr int KI_LG = 104960;
constexpr int KI_LB = 105472;
constexpr int KI_HR = 105984;
constexpr int KI_CS = 107008;
constexpr int KI_SM = 107520;

__global__ void __launch_bounds__(256) k_input(
        const float* __restrict__ x, const float* __restrict__ Wi,
        const float* __restrict__ bi, const float* __restrict__ lg,
        const float* __restrict__ lb) {
    extern __shared__ __align__(16) unsigned char smem[];
    const uint32_t sb = smem_to_u32(smem);
    const int tid = threadIdx.x, wid = tid >> 5, lane = tid & 31;
    const int j0 = (wid & 3) * 16, nh = wid >> 2;
    const int rg = lane >> 2, c2 = (lane & 3) * 2;

    for (int u = 0; u < 16; u++) {
        int idx = u * 256 + tid;
        int o = idx >> 5, c4 = (idx & 31) * 4;
        float4 v = *reinterpret_cast<const float4*>(Wi + o * C_ + c4);
        uint2 h, l; cvt_split4(v, h, l);
        uint32_t so = (uint32_t)(o * TSTR + c4) * 2;
        *reinterpret_cast<uint2*>(smem + KI_WH + so) = h;
        *reinterpret_cast<uint2*>(smem + KI_WL + so) = l;
    }
    if (tid < 128) {
        reinterpret_cast<float*>(smem + KI_BI)[tid] = bi[tid];
        reinterpret_cast<float*>(smem + KI_LG)[tid] = lg[tid];
        reinterpret_cast<float*>(smem + KI_LB)[tid] = lb[tid];
    }

    const uint32_t a_off = (uint32_t)((lane & 15) * TSTR + ((lane >> 4) << 3)) * 2;
    const uint32_t b_off = (uint32_t)((((lane >> 4) << 3) + (lane & 7)) * TSTR
                                      + (((lane >> 3) & 1) << 3)) * 2;
    const float* bi_s = reinterpret_cast<const float*>(smem + KI_BI);
    const float* lg_s = reinterpret_cast<const float*>(smem + KI_LG);
    const float* lb_s = reinterpret_cast<const float*>(smem + KI_LB);
    float* cs_s = reinterpret_cast<float*>(smem + KI_CS);
    float2* hr = reinterpret_cast<float2*>(smem + KI_HR);

    for (int p = blockIdx.x; p < B_ * N_; p += gridDim.x) {
        const int bb = p >> 6, ii = p & 63;
        __syncthreads();
        if (tid < 128) cs_s[tid] = 0.f;
        {
            const float* xs = x + (size_t)p * (N_ * C_);
            for (int u = 0; u < 8; u++) {
                int idx = u * 256 + tid;
                int r = idx >> 5, c4 = (idx & 31) * 4;
                float4 v = *reinterpret_cast<const float4*>(xs + r * C_ + c4);
                uint2 h, l; cvt_split4(v, h, l);
                uint32_t so = (uint32_t)(r * TSTR + c4) * 2;
                *reinterpret_cast<uint2*>(smem + KI_XH + so) = h;
                *reinterpret_cast<uint2*>(smem + KI_XL + so) = l;
            }
        }
        __syncthreads();

        float acc[8][4];
#pragma unroll
        for (int nt = 0; nt < 8; nt++)
#pragma unroll
            for (int q = 0; q < 4; q++) acc[nt][q] = 0.f;

#pragma unroll 1
        for (int kt = 0; kt < 8; kt++) {
            const uint32_t kb = kt * 32;
            const uint32_t arow = (uint32_t)(j0 * TSTR) * 2 + a_off + kb;
            uint32_t xh[4], xl[4];
            ldsm4(xh, sb + KI_XH + arow);
            ldsm4(xl, sb + KI_XL + arow);
#pragma unroll
            for (int np = 0; np < 4; np++) {
                const uint32_t brow =
                    (uint32_t)((nh * 64 + np * 16) * TSTR) * 2 + b_off + kb;
                uint32_t wh[4], wl[4];
                ldsm4(wh, sb + KI_WH + brow);
                ldsm4(wl, sb + KI_WL + brow);
#pragma unroll
                for (int e = 0; e < 2; e++) {
                    float* d = acc[np * 2 + e];
                    const int rgi = e * 2;
                    mma16816(d, xh, wh[rgi], wh[rgi + 1]);
                    mma16816(d, xh, wl[rgi], wl[rgi + 1]);
                    mma16816(d, xl, wh[rgi], wh[rgi + 1]);
                }
            }
        }

        // ---- epilogue: bias + GELU, LN stats ----
        float sa = 0.f, ssa = 0.f, sbm = 0.f, ssb = 0.f;
#pragma unroll
        for (int nt = 0; nt < 8; nt++) {
            const int o = nh * 64 + nt * 8 + c2;
            const float b0 = bi_s[o], b1 = bi_s[o + 1];
            acc[nt][0] = gelu_exact(acc[nt][0] + b0);
            acc[nt][1] = gelu_exact(acc[nt][1] + b1);
            acc[nt][2] = gelu_exact(acc[nt][2] + b0);
            acc[nt][3] = gelu_exact(acc[nt][3] + b1);
            sa  += acc[nt][0] + acc[nt][1];
            ssa += acc[nt][0] * acc[nt][0] + acc[nt][1] * acc[nt][1];
            sbm += acc[nt][2] + acc[nt][3];
            ssb += acc[nt][2] * acc[nt][2] + acc[nt][3] * acc[nt][3];
        }
#pragma unroll
        for (int off = 1; off <= 2; off <<= 1) {
            sa  += __shfl_xor_sync(0xffffffffu, sa,  off);
            ssa += __shfl_xor_sync(0xffffffffu, ssa, off);
            sbm += __shfl_xor_sync(0xffffffffu, sbm, off);
            ssb += __shfl_xor_sync(0xffffffffu, ssb, off);
        }
        if ((lane & 3) == 0) {
            hr[(j0 + rg) * 2 + nh]     = make_float2(sa, ssa);
            hr[(j0 + rg + 8) * 2 + nh] = make_float2(sbm, ssb);
        }
        __syncthreads();
        const int ja = j0 + rg, jb = j0 + rg + 8;
        float2 ha0 = hr[ja * 2 + 0], ha1 = hr[ja * 2 + 1];
        float2 hb0 = hr[jb * 2 + 0], hb1 = hr[jb * 2 + 1];
        const float mua = (ha0.x + ha1.x) * (1.0f / C_);
        const float inva = rsqrtf((ha0.y + ha1.y) * (1.0f / C_) - mua * mua + LN_EPS);
        const float mub = (hb0.x + hb1.x) * (1.0f / C_);
        const float invb = rsqrtf((hb0.y + hb1.y) * (1.0f / C_) - mub * mub + LN_EPS);

        uint32_t* th32 = reinterpret_cast<uint32_t*>(g_t1h);
        uint32_t* tl32 = reinterpret_cast<uint32_t*>(g_t1l);
        const size_t rba = ((size_t)p * N_ + ja) * (C_ / 2);
        const size_t rbb = ((size_t)p * N_ + jb) * (C_ / 2);
        float* colA = g_colsum + (size_t)(bb * N_ + ja) * C_;
        float* colB = g_colsum + (size_t)(bb * N_ + jb) * C_;
        const bool da = (ja == ii), db = (jb == ii);
#pragma unroll
        for (int nt = 0; nt < 8; nt++) {
            const int o = nh * 64 + nt * 8 + c2;
            const float g0 = lg_s[o], g1 = lg_s[o + 1];
            const float z0 = lb_s[o], z1 = lb_s[o + 1];
            float n0 = (acc[nt][0] - mua) * inva * g0 + z0;
            float n1 = (acc[nt][1] - mua) * inva * g1 + z1;
            float n2 = (acc[nt][2] - mub) * invb * g0 + z0;
            float n3 = (acc[nt][3] - mub) * invb * g1 + z1;
            uint32_t lo;
            uint32_t hi = split_pack(n0, n1, lo);
            th32[rba + (o >> 1)] = hi; tl32[rba + (o >> 1)] = lo;
            hi = split_pack(n2, n3, lo);
            th32[rbb + (o >> 1)] = hi; tl32[rbb + (o >> 1)] = lo;
            // col sums (over i, across tiles) — spread-address REDG
            atomicAdd(colA + o,     n0);
            atomicAdd(colA + o + 1, n1);
            atomicAdd(colB + o,     n2);
            atomicAdd(colB + o + 1, n3);
            // diag rows (j == i) — direct store
            if (da) { g_diag[p * C_ + o] = n0; g_diag[p * C_ + o + 1] = n1; }
            if (db) { g_diag[p * C_ + o] = n2; g_diag[p * C_ + o + 1] = n3; }
            // row sums (over j within tile)
            float cs0 = n0 + n2, cs1 = n1 + n3;
#pragma unroll
            for (int off = 4; off <= 16; off <<= 1) {
                cs0 += __shfl_xor_sync(0xffffffffu, cs0, off);
                cs1 += __shfl_xor_sync(0xffffffffu, cs1, off);
            }
            if (rg == 0) {
                atomicAdd(&cs_s[o], cs0);
                atomicAdd(&cs_s[o + 1], cs1);
            }
        }
        __syncthreads();
        if (tid < 128) g_row[p * C_ + tid] = cs_s[tid] * (1.0f / N_);
    }
}

// ---------------- K3: A,Bv,D + Cc,Ec ----------------------------------------
__global__ void __launch_bounds__(512) k_abd_ce() {
    const int tid = threadIdx.x;
    if (blockIdx.x < 128) {
        __shared__ float s_in[3 * 16 * C_];
        float* sd = s_in;
        float* sr = s_in + 16 * C_;
        float* sc = s_in + 32 * C_;
        const int rb = blockIdx.x * 16;
        for (int idx = tid; idx < 16 * C_; idx += 512) {
            sd[idx] = g_diag[rb * C_ + idx];
            sr[idx] = g_row [rb * C_ + idx];
            sc[idx] = g_colsum[rb * C_ + idx] * (1.0f / N_);   // raw sums -> means
        }
        __syncthreads();
        const int o = tid & 127, grp = tid >> 7;
        const float* W[9] = {
            g_WT + 2 * C_ * C_, g_WT + 4 * C_ * C_, g_WT + 6 * C_ * C_,
            g_WT + 3 * C_ * C_, g_WT + 5 * C_ * C_, g_WT + 7 * C_ * C_,
            g_WT + 10 * C_ * C_, g_WT + 11 * C_ * C_, g_WT + 12 * C_ * C_
        };
        float acc[4][3];
#pragma unroll
        for (int r = 0; r < 4; r++) { acc[r][0] = acc[r][1] = acc[r][2] = 0.f; }
#pragma unroll 1
        for (int c0 = 0; c0 < C_; c0 += 4) {
            float w[4][9];
#pragma unroll
            for (int u = 0; u < 4; u++) {
                int wi = (c0 + u) * C_ + o;
#pragma unroll
                for (int m = 0; m < 9; m++) w[u][m] = W[m][wi];
            }
#pragma unroll
            for (int u = 0; u < 4; u++) {
                int c = c0 + u;
#pragma unroll
                for (int r = 0; r < 4; r++) {
                    int rr = grp * 4 + r;
                    float d = sd[rr * C_ + c], ro = sr[rr * C_ + c], co = sc[rr * C_ + c];
                    acc[r][0] = fmaf(w[u][0], d, fmaf(w[u][1], ro, fmaf(w[u][2], co, acc[r][0])));
                    acc[r][1] = fmaf(w[u][3], d, fmaf(w[u][4], ro, fmaf(w[u][5], co, acc[r][1])));
                    acc[r][2] = fmaf(w[u][6], d, fmaf(w[u][7], ro, fmaf(w[u][8], co, acc[r][2])));
                }
            }
        }
#pragma unroll
        for (int r = 0; r < 4; r++) {
            int rr = rb + grp * 4 + r;
            g_A [rr * C_ + o] = acc[r][0];
            g_Bv[rr * C_ + o] = acc[r][1];
            g_D [rr * C_ + o] = acc[r][2];
        }
    } else {
        __shared__ float str[C_], sto[C_], red[8][C_];
        const int b = blockIdx.x - 128;
        if (tid < C_) {
            float st = 0.f, so = 0.f;
#pragma unroll 4
            for (int q = 0; q < N_; q++) {
                st += g_diag[(b * N_ + q) * C_ + tid];
                so += g_row [(b * N_ + q) * C_ + tid];
            }
            str[tid] = st * (1.0f / N_);
            sto[tid] = so * (1.0f / N_);
        }
        __syncthreads();
        const int o = tid & 127, grp = tid >> 7;
        const float* W8  = g_WT + 8  * C_ * C_;
        const float* W9  = g_WT + 9  * C_ * C_;
        const float* W13 = g_WT + 13 * C_ * C_;
        const float* W14 = g_WT + 14 * C_ * C_;
        float a = 0.f, e = 0.f;
        for (int c = grp * 32; c < grp * 32 + 32; c++) {
            int wi = c * C_ + o;
            float tr = str[c], to = sto[c];
            a = fmaf(W8 [wi], tr, fmaf(W9 [wi], to, a));
            e = fmaf(W13[wi], tr, fmaf(W14[wi], to, e));
        }
        red[grp][o] = a; red[4 + grp][o] = e;
        __syncthreads();
        if (tid < C_) {
            g_Cc[b * C_ + tid] = red[0][tid] + red[1][tid] + red[2][tid] + red[3][tid];
            g_Ec[b * C_ + tid] = red[4][tid] + red[5][tid] + red[6][tid] + red[7][tid];
        }
    }
}

// ---------------- K4: warp-MMA main GEMM pair (R7 structure + prefetch) -----
constexpr int SMB_W0H = 0;
constexpr int SMB_W0L = 34816;
constexpr int SMB_W1H = 69632;
constexpr int SMB_W1L = 104448;
constexpr int SMB_T1H = 139264;
constexpr int SMB_T1L = 156672;
constexpr int SMB_T2H = 174080;
constexpr int SMB_T2L = 191488;
constexpr int SM_MAIN = 208896;

__global__ void __launch_bounds__(256) k_main(float* __restrict__ out) {
    extern __shared__ __align__(16) unsigned char smem[];
    const uint32_t sb = smem_to_u32(smem);
    const int tid = threadIdx.x, wid = tid >> 5, lane = tid & 31;
    const int j0 = (wid & 3) * 16;
    const int nh = wid >> 2;
    const int rg = lane >> 2, c2 = (lane & 3) * 2;

    {   // resident weights
        const uint4* src = reinterpret_cast<const uint4*>(g_Wb);
        uint4* dst = reinterpret_cast<uint4*>(smem);
        for (int i = tid; i < 4 * WSEG * 2 / 16; i += 256) dst[i] = src[i];
    }

    const uint32_t a_off = (uint32_t)((lane & 15) * TSTR + ((lane >> 4) << 3)) * 2;
    const uint32_t b_off = (uint32_t)((((lane >> 4) << 3) + (lane & 7)) * TSTR
                                      + (((lane >> 3) & 1) << 3)) * 2;

    auto stage = [&](int p) {
        const int b = p >> 6, i = p & 63;
        const char* s1h = reinterpret_cast<const char*>(g_t1h + (size_t)p * (N_ * C_));
        const char* s1l = reinterpret_cast<const char*>(g_t1l + (size_t)p * (N_ * C_));
#pragma unroll
        for (int u = 0; u < 4; u++) {
            int ch = u * 256 + tid;
            int r = ch >> 4, c = ch & 15;
            uint32_t dso = (uint32_t)(r * TSTR + c * 8) * 2;
            CP_ASYNC16(sb + SMB_T1H + dso, s1h + ch * 16);
            CP_ASYNC16(sb + SMB_T1L + dso, s1l + ch * 16);
            const size_t r2 = ((size_t)((b * N_ + r) * N_ + i)) * C_;
            CP_ASYNC16(sb + SMB_T2H + dso, reinterpret_cast<const char*>(g_t1h + r2) + c * 16);
            CP_ASYNC16(sb + SMB_T2L + dso, reinterpret_cast<const char*>(g_t1l + r2) + c * 16);
        }
    };

    int p = blockIdx.x;
    if (p < B_ * N_) { stage(p); CP_COMMIT(); }
    CP_WAIT0();
    __syncthreads();

    for (; p < B_ * N_; p += gridDim.x) {
        const int b = p >> 6, i = p & 63;

        // ---- prefetch epilogue broadcasts (retire under the mainloop) ----
        float addq[8][2], diaq[8][2];
        {
            const float* Ap  = g_A  + (size_t)p * C_;
            const float* Ccp = g_Cc + (size_t)b * C_;
            const float* Dp  = g_D  + (size_t)p * C_;
            const float* Ep  = g_Ec + (size_t)b * C_;
#pragma unroll
            for (int nt = 0; nt < 8; nt++) {
                const int o = nh * 64 + nt * 8 + c2;
                float2 av = *reinterpret_cast<const float2*>(Ap + o);
                float2 cv = *reinterpret_cast<const float2*>(Ccp + o);
                float2 dd = *reinterpret_cast<const float2*>(Dp + o);
                float2 ee = *reinterpret_cast<const float2*>(Ep + o);
                addq[nt][0] = av.x + cv.x; addq[nt][1] = av.y + cv.y;
                diaq[nt][0] = dd.x + ee.x; diaq[nt][1] = dd.y + ee.y;
            }
        }

        // ---- MMA mainloop (R7 structure, no B double-buffer) ----
        float acc[8][4];
#pragma unroll
        for (int nt = 0; nt < 8; nt++)
#pragma unroll
            for (int q = 0; q < 4; q++) acc[nt][q] = 0.f;

#pragma unroll 1
        for (int kt = 0; kt < 8; kt++) {
            const uint32_t kb = kt * 32;
            const uint32_t arow = (uint32_t)(j0 * TSTR) * 2 + a_off + kb;
            uint32_t a1h[4], a1l[4], a2h[4], a2l[4];
            ldsm4(a1h, sb + SMB_T1H + arow);
            ldsm4(a1l, sb + SMB_T1L + arow);
            ldsm4(a2h, sb + SMB_T2H + arow);
            ldsm4(a2l, sb + SMB_T2L + arow);
#pragma unroll
            for (int np = 0; np < 4; np++) {
                const uint32_t brow =
                    (uint32_t)((nh * 64 + np * 16) * TSTR) * 2 + b_off + kb;
                uint32_t w0h[4], w0l[4], w1h[4], w1l[4];
                ldsm4(w0h, sb + SMB_W0H + brow);
                ldsm4(w0l, sb + SMB_W0L + brow);
                ldsm4(w1h, sb + SMB_W1H + brow);
                ldsm4(w1l, sb + SMB_W1L + brow);
#pragma unroll
                for (int e = 0; e < 2; e++) {
                    float* d = acc[np * 2 + e];
                    const int rgi = e * 2;
                    mma16816(d, a1h, w0h[rgi], w0h[rgi + 1]);
                    mma16816(d, a1h, w0l[rgi], w0l[rgi + 1]);
                    mma16816(d, a1l, w0h[rgi], w0h[rgi + 1]);
                    mma16816(d, a2h, w1h[rgi], w1h[rgi + 1]);
                    mma16816(d, a2h, w1l[rgi], w1l[rgi + 1]);
                    mma16816(d, a2l, w1h[rgi], w1h[rgi + 1]);
                }
            }
        }
        __syncthreads();
        const int pn = p + gridDim.x;
        if (pn < B_ * N_) { stage(pn); CP_COMMIT(); }

        // ---- epilogue ----
        {
            const int ja = j0 + rg, jb = j0 + rg + 8;
            const float* Bva = g_Bv + ((size_t)(b * N_ + ja)) * C_;
            const float* Bvb = g_Bv + ((size_t)(b * N_ + jb)) * C_;
            float* outa = out + ((size_t)p * N_ + ja) * C_;
            float* outb = out + ((size_t)p * N_ + jb) * C_;
            const bool da = (ja == i), db = (jb == i);
#pragma unroll
            for (int nt = 0; nt < 8; nt++) {
                const int o = nh * 64 + nt * 8 + c2;
                {
                    float2 bv = *reinterpret_cast<const float2*>(Bva + o);
                    float e0 = acc[nt][0] + addq[nt][0] + bv.x;
                    float e1 = acc[nt][1] + addq[nt][1] + bv.y;
                    if (da) { e0 += diaq[nt][0]; e1 += diaq[nt][1]; }
                    float2 o2; o2.x = gelu_exact(e0); o2.y = gelu_exact(e1);
                    *reinterpret_cast<float2*>(outa + o) = o2;
                }
                {
                    float2 bv = *reinterpret_cast<const float2*>(Bvb + o);
                    float e0 = acc[nt][2] + addq[nt][0] + bv.x;
                    float e1 = acc[nt][3] + addq[nt][1] + bv.y;
                    if (db) { e0 += diaq[nt][0]; e1 += diaq[nt][1]; }
                    float2 o2; o2.x = gelu_exact(e0); o2.y = gelu_exact(e1);
                    *reinterpret_cast<float2*>(outb + o) = o2;
                }
            }
        }
        CP_WAIT0();
        __syncthreads();
    }
}

} // anonymous namespace

// ---------------- launch -----------------------------------------------------
extern "C" void kernel_launch(void* const* d_in, const int* in_sizes, int n_in,
                              void* d_out, int out_size) {
    const float* x   = (const float*)d_in[0];
    const float* Wi  = (const float*)d_in[3];
    const float* bi  = (const float*)d_in[4];
    const float* lg  = (const float*)d_in[5];
    const float* lb  = (const float*)d_in[6];
    const float* c00 = (const float*)d_in[7];
    const float* c01 = (const float*)d_in[8];
    const float* c10 = (const float*)d_in[9];
    const float* c11 = (const float*)d_in[10];
    float* out = (float*)d_out;

    cudaFuncSetAttribute(k_input, cudaFuncAttributeMaxDynamicSharedMemorySize, KI_SM);
    cudaFuncSetAttribute(k_main,  cudaFuncAttributeMaxDynamicSharedMemorySize, SM_MAIN);

    k_mix   <<<248, 512>>>(c00, c01, c10, c11);   // coeffs + zero col accumulators
    k_input <<<296, 256, KI_SM>>>(x, Wi, bi, lg, lb);  // + col atomics + diag
    k_abd_ce<<<160, 512>>>();
    k_main  <<<148, 256, SM_MAIN>>>(out);
}

// round 10
// speedup vs baseline: 1.5081x; 1.5081x over previous
#include <cuda_runtime.h>
#include <cuda_bf16.h>
#include <math.h>
#include <stdint.h>

namespace {

constexpr int B_ = 32;
constexpr int N_ = 64;
constexpr int C_ = 128;
constexpr int M_ = 15;
constexpr int E_ = B_ * N_ * N_;   // 131072
constexpr float LN_EPS = 1e-5f;
constexpr int TSTR = 136;          // padded bf16 row stride (272B: conflict-free ldmatrix)
constexpr int WSEG = 128 * TSTR;   // elements per weight segment

// ---------------- device scratch --------------------------------------------
__device__ __align__(16) __nv_bfloat16 g_t1h[(size_t)E_ * C_];
__device__ __align__(16) __nv_bfloat16 g_t1l[(size_t)E_ * C_];
__device__ __align__(16) float g_row [B_ * N_ * C_];
__device__ __align__(16) float g_col [B_ * N_ * C_];
__device__ __align__(16) float g_diag[B_ * N_ * C_];
__device__ __align__(16) float g_A [B_ * N_ * C_];
__device__ __align__(16) float g_Bv[B_ * N_ * C_];
__device__ __align__(16) float g_D [B_ * N_ * C_];
__device__ __align__(16) float g_Cc[B_ * C_];
__device__ __align__(16) float g_Ec[B_ * C_];
__device__ __align__(16) float g_WT[M_ * C_ * C_];          // [m][c][o]
__device__ __align__(16) __nv_bfloat16 g_Wb[4 * WSEG];      // {W0hi,W0lo,W1hi,W1lo}

// ---------------- helpers ----------------------------------------------------
__device__ __forceinline__ float gelu_exact(float v) {
    return 0.5f * v * (1.0f + erff(v * 0.70710678118654752440f));
}
__device__ __forceinline__ uint32_t smem_to_u32(const void* p) {
    uint32_t a;
    asm("{ .reg .u64 t; cvta.to.shared.u64 t, %1; cvt.u32.u64 %0, t; }" : "=r"(a) : "l"(p));
    return a;
}
__device__ __forceinline__ void ldsm4(uint32_t* r, uint32_t addr) {
    asm volatile("ldmatrix.sync.aligned.m8n8.x4.shared.b16 {%0,%1,%2,%3}, [%4];"
                 : "=r"(r[0]), "=r"(r[1]), "=r"(r[2]), "=r"(r[3]) : "r"(addr));
}
__device__ __forceinline__ void mma16816(float* d, const uint32_t* a,
                                         uint32_t b0, uint32_t b1) {
    asm volatile("mma.sync.aligned.m16n8k16.row.col.f32.bf16.bf16.f32 "
                 "{%0,%1,%2,%3}, {%4,%5,%6,%7}, {%8,%9}, {%0,%1,%2,%3};"
                 : "+f"(d[0]), "+f"(d[1]), "+f"(d[2]), "+f"(d[3])
                 : "r"(a[0]), "r"(a[1]), "r"(a[2]), "r"(a[3]), "r"(b0), "r"(b1));
}
__device__ __forceinline__ void cvt_split4(float4 v, uint2& h, uint2& l) {
    __nv_bfloat162 h0 = __floats2bfloat162_rn(v.x, v.y);
    __nv_bfloat162 h1 = __floats2bfloat162_rn(v.z, v.w);
    float r0 = v.x - __bfloat162float(h0.x);
    float r1 = v.y - __bfloat162float(h0.y);
    float r2 = v.z - __bfloat162float(h1.x);
    float r3 = v.w - __bfloat162float(h1.y);
    __nv_bfloat162 l0 = __floats2bfloat162_rn(r0, r1);
    __nv_bfloat162 l1 = __floats2bfloat162_rn(r2, r3);
    h.x = *reinterpret_cast<uint32_t*>(&h0); h.y = *reinterpret_cast<uint32_t*>(&h1);
    l.x = *reinterpret_cast<uint32_t*>(&l0); l.y = *reinterpret_cast<uint32_t*>(&l1);
}
__device__ __forceinline__ uint32_t split_pack(float a, float b, uint32_t& lo) {
    __nv_bfloat162 h = __floats2bfloat162_rn(a, b);
    float r0 = a - __bfloat162float(h.x);
    float r1 = b - __bfloat162float(h.y);
    __nv_bfloat162 l = __floats2bfloat162_rn(r0, r1);
    lo = *reinterpret_cast<uint32_t*>(&l);
    return *reinterpret_cast<uint32_t*>(&h);
}

#define CP_ASYNC16(dst, src) \
    asm volatile("cp.async.cg.shared.global [%0], [%1], 16;" :: "r"(dst), "l"(src))
#define CP_COMMIT() asm volatile("cp.async.commit_group;" ::: "memory")
#define CP_WAIT0()  asm volatile("cp.async.wait_group 0;" ::: "memory")

// ---------------- K1: warp-MMA input GEMM + GELU + LN + row means (R7) ------
constexpr int KI_WH = 0;
constexpr int KI_WL = 34816;
constexpr int KI_XH = 69632;
constexpr int KI_XL = 87040;
constexpr int KI_BI = 104448;
constexpr int KI_LG = 104960;
constexpr int KI_LB = 105472;
constexpr int KI_HR = 105984;
constexpr int KI_CS = 107008;
constexpr int KI_SM = 107520;

__global__ void __launch_bounds__(256) k_input(
        const float* __restrict__ x, const float* __restrict__ Wi,
        const float* __restrict__ bi, const float* __restrict__ lg,
        const float* __restrict__ lb) {
    extern __shared__ __align__(16) unsigned char smem[];
    const uint32_t sb = smem_to_u32(smem);
    const int tid = threadIdx.x, wid = tid >> 5, lane = tid & 31;
    const int j0 = (wid & 3) * 16, nh = wid >> 2;
    const int rg = lane >> 2, c2 = (lane & 3) * 2;

    for (int u = 0; u < 16; u++) {
        int idx = u * 256 + tid;
        int o = idx >> 5, c4 = (idx & 31) * 4;
        float4 v = *reinterpret_cast<const float4*>(Wi + o * C_ + c4);
        uint2 h, l; cvt_split4(v, h, l);
        uint32_t so = (uint32_t)(o * TSTR + c4) * 2;
        *reinterpret_cast<uint2*>(smem + KI_WH + so) = h;
        *reinterpret_cast<uint2*>(smem + KI_WL + so) = l;
    }
    if (tid < 128) {
        reinterpret_cast<float*>(smem + KI_BI)[tid] = bi[tid];
        reinterpret_cast<float*>(smem + KI_LG)[tid] = lg[tid];
        reinterpret_cast<float*>(smem + KI_LB)[tid] = lb[tid];
    }

    const uint32_t a_off = (uint32_t)((lane & 15) * TSTR + ((lane >> 4) << 3)) * 2;
    const uint32_t b_off = (uint32_t)((((lane >> 4) << 3) + (lane & 7)) * TSTR
                                      + (((lane >> 3) & 1) << 3)) * 2;
    const float* bi_s = reinterpret_cast<const float*>(smem + KI_BI);
    const float* lg_s = reinterpret_cast<const float*>(smem + KI_LG);
    const float* lb_s = reinterpret_cast<const float*>(smem + KI_LB);
    float* cs_s = reinterpret_cast<float*>(smem + KI_CS);
    float2* hr = reinterpret_cast<float2*>(smem + KI_HR);

    for (int p = blockIdx.x; p < B_ * N_; p += gridDim.x) {
        __syncthreads();
        if (tid < 128) cs_s[tid] = 0.f;
        {
            const float* xs = x + (size_t)p * (N_ * C_);
            for (int u = 0; u < 8; u++) {
                int idx = u * 256 + tid;
                int r = idx >> 5, c4 = (idx & 31) * 4;
                float4 v = *reinterpret_cast<const float4*>(xs + r * C_ + c4);
                uint2 h, l; cvt_split4(v, h, l);
                uint32_t so = (uint32_t)(r * TSTR + c4) * 2;
                *reinterpret_cast<uint2*>(smem + KI_XH + so) = h;
                *reinterpret_cast<uint2*>(smem + KI_XL + so) = l;
            }
        }
        __syncthreads();

        float acc[8][4];
#pragma unroll
        for (int nt = 0; nt < 8; nt++)
#pragma unroll
            for (int q = 0; q < 4; q++) acc[nt][q] = 0.f;

#pragma unroll 1
        for (int kt = 0; kt < 8; kt++) {
            const uint32_t kb = kt * 32;
            const uint32_t arow = (uint32_t)(j0 * TSTR) * 2 + a_off + kb;
            uint32_t xh[4], xl[4];
            ldsm4(xh, sb + KI_XH + arow);
            ldsm4(xl, sb + KI_XL + arow);
#pragma unroll
            for (int np = 0; np < 4; np++) {
                const uint32_t brow =
                    (uint32_t)((nh * 64 + np * 16) * TSTR) * 2 + b_off + kb;
                uint32_t wh[4], wl[4];
                ldsm4(wh, sb + KI_WH + brow);
                ldsm4(wl, sb + KI_WL + brow);
#pragma unroll
                for (int e = 0; e < 2; e++) {
                    float* d = acc[np * 2 + e];
                    const int rgi = e * 2;
                    mma16816(d, xh, wh[rgi], wh[rgi + 1]);
                    mma16816(d, xh, wl[rgi], wl[rgi + 1]);
                    mma16816(d, xl, wh[rgi], wh[rgi + 1]);
                }
            }
        }

        // ---- epilogue: bias + GELU, LN stats ----
        float sa = 0.f, ssa = 0.f, sbm = 0.f, ssb = 0.f;
#pragma unroll
        for (int nt = 0; nt < 8; nt++) {
            const int o = nh * 64 + nt * 8 + c2;
            const float b0 = bi_s[o], b1 = bi_s[o + 1];
            acc[nt][0] = gelu_exact(acc[nt][0] + b0);
            acc[nt][1] = gelu_exact(acc[nt][1] + b1);
            acc[nt][2] = gelu_exact(acc[nt][2] + b0);
            acc[nt][3] = gelu_exact(acc[nt][3] + b1);
            sa  += acc[nt][0] + acc[nt][1];
            ssa += acc[nt][0] * acc[nt][0] + acc[nt][1] * acc[nt][1];
            sbm += acc[nt][2] + acc[nt][3];
            ssb += acc[nt][2] * acc[nt][2] + acc[nt][3] * acc[nt][3];
        }
#pragma unroll
        for (int off = 1; off <= 2; off <<= 1) {
            sa  += __shfl_xor_sync(0xffffffffu, sa,  off);
            ssa += __shfl_xor_sync(0xffffffffu, ssa, off);
            sbm += __shfl_xor_sync(0xffffffffu, sbm, off);
            ssb += __shfl_xor_sync(0xffffffffu, ssb, off);
        }
        if ((lane & 3) == 0) {
            hr[(j0 + rg) * 2 + nh]     = make_float2(sa, ssa);
            hr[(j0 + rg + 8) * 2 + nh] = make_float2(sbm, ssb);
        }
        __syncthreads();
        const int ja = j0 + rg, jb = j0 + rg + 8;
        float2 ha0 = hr[ja * 2 + 0], ha1 = hr[ja * 2 + 1];
        float2 hb0 = hr[jb * 2 + 0], hb1 = hr[jb * 2 + 1];
        const float mua = (ha0.x + ha1.x) * (1.0f / C_);
        const float inva = rsqrtf((ha0.y + ha1.y) * (1.0f / C_) - mua * mua + LN_EPS);
        const float mub = (hb0.x + hb1.x) * (1.0f / C_);
        const float invb = rsqrtf((hb0.y + hb1.y) * (1.0f / C_) - mub * mub + LN_EPS);

        uint32_t* th32 = reinterpret_cast<uint32_t*>(g_t1h);
        uint32_t* tl32 = reinterpret_cast<uint32_t*>(g_t1l);
        const size_t rba = ((size_t)p * N_ + ja) * (C_ / 2);
        const size_t rbb = ((size_t)p * N_ + jb) * (C_ / 2);
#pragma unroll
        for (int nt = 0; nt < 8; nt++) {
            const int o = nh * 64 + nt * 8 + c2;
            const float g0 = lg_s[o], g1 = lg_s[o + 1];
            const float z0 = lb_s[o], z1 = lb_s[o + 1];
            float n0 = (acc[nt][0] - mua) * inva * g0 + z0;
            float n1 = (acc[nt][1] - mua) * inva * g1 + z1;
            float n2 = (acc[nt][2] - mub) * invb * g0 + z0;
            float n3 = (acc[nt][3] - mub) * invb * g1 + z1;
            uint32_t lo;
            uint32_t hi = split_pack(n0, n1, lo);
            th32[rba + (o >> 1)] = hi; tl32[rba + (o >> 1)] = lo;
            hi = split_pack(n2, n3, lo);
            th32[rbb + (o >> 1)] = hi; tl32[rbb + (o >> 1)] = lo;
            float cs0 = n0 + n2, cs1 = n1 + n3;
#pragma unroll
            for (int off = 4; off <= 16; off <<= 1) {
                cs0 += __shfl_xor_sync(0xffffffffu, cs0, off);
                cs1 += __shfl_xor_sync(0xffffffffu, cs1, off);
            }
            if (rg == 0) {
                atomicAdd(&cs_s[o], cs0);
                atomicAdd(&cs_s[o + 1], cs1);
            }
        }
        __syncthreads();
        if (tid < 128) g_row[p * C_ + tid] = cs_s[tid] * (1.0f / N_);
    }
}

// ---------------- K2: coeffs + COALESCED col means + diag -------------------
// bx <  120: coefficient build (8 elems/thread).
// bx >= 120: col/diag — block = (b, 8 consecutive q rows); per i-iteration the
//            8 warps read 2KB contiguous hi + 2KB lo; register accumulation.
__global__ void __launch_bounds__(256) k_colmix(
        const float* __restrict__ c00, const float* __restrict__ c01,
        const float* __restrict__ c10, const float* __restrict__ c11) {
    const int bx = blockIdx.x, tid = threadIdx.x;
    if (bx < 120) {
#pragma unroll
        for (int u = 0; u < 8; u++) {
            int idx = bx * 2048 + u * 256 + tid;
            int o = idx & 127, c = (idx >> 7) & 127, m = idx >> 14;
            float v = c00[o * M_ + m] * c10[o * C_ + c] + c01[c * M_ + m] * c11[o * C_ + c];
            g_WT[idx] = v;
            if (m < 2) {
                __nv_bfloat16 hb = __float2bfloat16_rn(v);
                float rr = v - __bfloat162float(hb);
                __nv_bfloat16 lo = __float2bfloat16_rn(rr);
                g_Wb[(m * 2 + 0) * WSEG + o * TSTR + c] = hb;
                g_Wb[(m * 2 + 1) * WSEG + o * TSTR + c] = lo;
            }
        }
    } else {
        const int cb = bx - 120;              // 0..255
        const int b = cb >> 3, qg = cb & 7;
        const int ql = tid >> 5, lane = tid & 31;
        const int q = qg * 8 + ql;
        const int c0 = lane * 4;              // 4 channels per thread
        const uint2* th = reinterpret_cast<const uint2*>(g_t1h);
        const uint2* tl = reinterpret_cast<const uint2*>(g_t1l);
        // uint2 index of (b, i, q, c0): element idx / 4
        const size_t base = ((size_t)(b * N_) * N_ + q) * (C_ / 4) + (c0 >> 2);
        const size_t istep = (size_t)N_ * (C_ / 4);
        float s0 = 0.f, s1 = 0.f, s2 = 0.f, s3 = 0.f;
        float d0 = 0.f, d1 = 0.f, d2 = 0.f, d3 = 0.f;
#pragma unroll 4
        for (int i = 0; i < N_; i++) {
            uint2 hv = th[base + (size_t)i * istep];
            uint2 lv = tl[base + (size_t)i * istep];
            __nv_bfloat162 h0 = *reinterpret_cast<__nv_bfloat162*>(&hv.x);
            __nv_bfloat162 h1 = *reinterpret_cast<__nv_bfloat162*>(&hv.y);
            __nv_bfloat162 l0 = *reinterpret_cast<__nv_bfloat162*>(&lv.x);
            __nv_bfloat162 l1 = *reinterpret_cast<__nv_bfloat162*>(&lv.y);
            float v0 = __bfloat162float(h0.x) + __bfloat162float(l0.x);
            float v1 = __bfloat162float(h0.y) + __bfloat162float(l0.y);
            float v2 = __bfloat162float(h1.x) + __bfloat162float(l1.x);
            float v3 = __bfloat162float(h1.y) + __bfloat162float(l1.y);
            s0 += v0; s1 += v1; s2 += v2; s3 += v3;
            if (i == q) { d0 = v0; d1 = v1; d2 = v2; d3 = v3; }
        }
        float* cp = g_col  + (size_t)(b * N_ + q) * C_ + c0;
        float* dp = g_diag + (size_t)(b * N_ + q) * C_ + c0;
        cp[0] = s0 * (1.0f / N_); cp[1] = s1 * (1.0f / N_);
        cp[2] = s2 * (1.0f / N_); cp[3] = s3 * (1.0f / N_);
        dp[0] = d0; dp[1] = d1; dp[2] = d2; dp[3] = d3;
    }
}

// ---------------- K3: A,Bv,D + Cc,Ec (R7) -----------------------------------
__global__ void __launch_bounds__(512) k_abd_ce() {
    const int tid = threadIdx.x;
    if (blockIdx.x < 128) {
        __shared__ float s_in[3 * 16 * C_];
        float* sd = s_in;
        float* sr = s_in + 16 * C_;
        float* sc = s_in + 32 * C_;
        const int rb = blockIdx.x * 16;
        for (int idx = tid; idx < 16 * C_; idx += 512) {
            sd[idx] = g_diag[rb * C_ + idx];
            sr[idx] = g_row [rb * C_ + idx];
            sc[idx] = g_col [rb * C_ + idx];
        }
        __syncthreads();
        const int o = tid & 127, grp = tid >> 7;
        const float* W[9] = {
            g_WT + 2 * C_ * C_, g_WT + 4 * C_ * C_, g_WT + 6 * C_ * C_,
            g_WT + 3 * C_ * C_, g_WT + 5 * C_ * C_, g_WT + 7 * C_ * C_,
            g_WT + 10 * C_ * C_, g_WT + 11 * C_ * C_, g_WT + 12 * C_ * C_
        };
        float acc[4][3];
#pragma unroll
        for (int r = 0; r < 4; r++) { acc[r][0] = acc[r][1] = acc[r][2] = 0.f; }
#pragma unroll 1
        for (int c0 = 0; c0 < C_; c0 += 4) {
            float w[4][9];
#pragma unroll
            for (int u = 0; u < 4; u++) {
                int wi = (c0 + u) * C_ + o;
#pragma unroll
                for (int m = 0; m < 9; m++) w[u][m] = W[m][wi];
            }
#pragma unroll
            for (int u = 0; u < 4; u++) {
                int c = c0 + u;
#pragma unroll
                for (int r = 0; r < 4; r++) {
                    int rr = grp * 4 + r;
                    float d = sd[rr * C_ + c], ro = sr[rr * C_ + c], co = sc[rr * C_ + c];
                    acc[r][0] = fmaf(w[u][0], d, fmaf(w[u][1], ro, fmaf(w[u][2], co, acc[r][0])));
                    acc[r][1] = fmaf(w[u][3], d, fmaf(w[u][4], ro, fmaf(w[u][5], co, acc[r][1])));
                    acc[r][2] = fmaf(w[u][6], d, fmaf(w[u][7], ro, fmaf(w[u][8], co, acc[r][2])));
                }
            }
        }
#pragma unroll
        for (int r = 0; r < 4; r++) {
            int rr = rb + grp * 4 + r;
            g_A [rr * C_ + o] = acc[r][0];
            g_Bv[rr * C_ + o] = acc[r][1];
            g_D [rr * C_ + o] = acc[r][2];
        }
    } else {
        __shared__ float str[C_], sto[C_], red[8][C_];
        const int b = blockIdx.x - 128;
        if (tid < C_) {
            float st = 0.f, so = 0.f;
#pragma unroll 4
            for (int q = 0; q < N_; q++) {
                st += g_diag[(b * N_ + q) * C_ + tid];
                so += g_row [(b * N_ + q) * C_ + tid];
            }
            str[tid] = st * (1.0f / N_);
            sto[tid] = so * (1.0f / N_);
        }
        __syncthreads();
        const int o = tid & 127, grp = tid >> 7;
        const float* W8  = g_WT + 8  * C_ * C_;
        const float* W9  = g_WT + 9  * C_ * C_;
        const float* W13 = g_WT + 13 * C_ * C_;
        const float* W14 = g_WT + 14 * C_ * C_;
        float a = 0.f, e = 0.f;
        for (int c = grp * 32; c < grp * 32 + 32; c++) {
            int wi = c * C_ + o;
            float tr = str[c], to = sto[c];
            a = fmaf(W8 [wi], tr, fmaf(W9 [wi], to, a));
            e = fmaf(W13[wi], tr, fmaf(W14[wi], to, e));
        }
        red[grp][o] = a; red[4 + grp][o] = e;
        __syncthreads();
        if (tid < C_) {
            g_Cc[b * C_ + tid] = red[0][tid] + red[1][tid] + red[2][tid] + red[3][tid];
            g_Ec[b * C_ + tid] = red[4][tid] + red[5][tid] + red[6][tid] + red[7][tid];
        }
    }
}

// ---------------- K4: warp-MMA main GEMM pair (exact R7) --------------------
constexpr int SMB_W0H = 0;
constexpr int SMB_W0L = 34816;
constexpr int SMB_W1H = 69632;
constexpr int SMB_W1L = 104448;
constexpr int SMB_T1H = 139264;
constexpr int SMB_T1L = 156672;
constexpr int SMB_T2H = 174080;
constexpr int SMB_T2L = 191488;
constexpr int SM_MAIN = 208896;

__global__ void __launch_bounds__(256) k_main(float* __restrict__ out) {
    extern __shared__ __align__(16) unsigned char smem[];
    const uint32_t sb = smem_to_u32(smem);
    const int tid = threadIdx.x, wid = tid >> 5, lane = tid & 31;
    const int j0 = (wid & 3) * 16;
    const int nh = wid >> 2;

    {   // resident weights (prepacked split layout)
        const uint4* src = reinterpret_cast<const uint4*>(g_Wb);
        uint4* dst = reinterpret_cast<uint4*>(smem);
        for (int i = tid; i < 4 * WSEG * 2 / 16; i += 256) dst[i] = src[i];
    }

    const uint32_t a_off = (uint32_t)((lane & 15) * TSTR + ((lane >> 4) << 3)) * 2;
    const uint32_t b_off = (uint32_t)((((lane >> 4) << 3) + (lane & 7)) * TSTR
                                      + (((lane >> 3) & 1) << 3)) * 2;

    auto stage = [&](int p) {   // 16 cp.async x 16B per thread
        const int b = p >> 6, i = p & 63;
        const char* s1h = reinterpret_cast<const char*>(g_t1h + (size_t)p * (N_ * C_));
        const char* s1l = reinterpret_cast<const char*>(g_t1l + (size_t)p * (N_ * C_));
#pragma unroll
        for (int u = 0; u < 4; u++) {
            int ch = u * 256 + tid;         // 0..1023
            int r = ch >> 4, c = ch & 15;
            uint32_t dso = (uint32_t)(r * TSTR + c * 8) * 2;
            CP_ASYNC16(sb + SMB_T1H + dso, s1h + ch * 16);
            CP_ASYNC16(sb + SMB_T1L + dso, s1l + ch * 16);
            const size_t r2 = ((size_t)((b * N_ + r) * N_ + i)) * C_;
            CP_ASYNC16(sb + SMB_T2H + dso, reinterpret_cast<const char*>(g_t1h + r2) + c * 16);
            CP_ASYNC16(sb + SMB_T2L + dso, reinterpret_cast<const char*>(g_t1l + r2) + c * 16);
        }
    };

    int p = blockIdx.x;
    if (p < B_ * N_) { stage(p); CP_COMMIT(); }
    CP_WAIT0();
    __syncthreads();

    for (; p < B_ * N_; p += gridDim.x) {
        const int b = p >> 6, i = p & 63;

        // ---- MMA mainloop ----
        float acc[8][4];
#pragma unroll
        for (int nt = 0; nt < 8; nt++)
#pragma unroll
            for (int q = 0; q < 4; q++) acc[nt][q] = 0.f;

#pragma unroll 1
        for (int kt = 0; kt < 8; kt++) {
            const uint32_t kb = kt * 32;
            const uint32_t arow = (uint32_t)(j0 * TSTR) * 2 + a_off + kb;
            uint32_t a1h[4], a1l[4], a2h[4], a2l[4];
            ldsm4(a1h, sb + SMB_T1H + arow);
            ldsm4(a1l, sb + SMB_T1L + arow);
            ldsm4(a2h, sb + SMB_T2H + arow);
            ldsm4(a2l, sb + SMB_T2L + arow);
#pragma unroll
            for (int np = 0; np < 4; np++) {
                const uint32_t brow =
                    (uint32_t)((nh * 64 + np * 16) * TSTR) * 2 + b_off + kb;
                uint32_t w0h[4], w0l[4], w1h[4], w1l[4];
                ldsm4(w0h, sb + SMB_W0H + brow);
                ldsm4(w0l, sb + SMB_W0L + brow);
                ldsm4(w1h, sb + SMB_W1H + brow);
                ldsm4(w1l, sb + SMB_W1L + brow);
#pragma unroll
                for (int e = 0; e < 2; e++) {
                    float* d = acc[np * 2 + e];
                    const int rgi = e * 2;
                    mma16816(d, a1h, w0h[rgi], w0h[rgi + 1]);
                    mma16816(d, a1h, w0l[rgi], w0l[rgi + 1]);
                    mma16816(d, a1l, w0h[rgi], w0h[rgi + 1]);
                    mma16816(d, a2h, w1h[rgi], w1h[rgi + 1]);
                    mma16816(d, a2h, w1l[rgi], w1l[rgi + 1]);
                    mma16816(d, a2l, w1h[rgi], w1h[rgi + 1]);
                }
            }
        }
        __syncthreads();                      // all warps done reading T smem
        const int pn = p + gridDim.x;
        if (pn < B_ * N_) { stage(pn); CP_COMMIT(); }   // prefetch overlaps epilogue

        // ---- epilogue: broadcasts + GELU + store ----
        {
            const int rg = lane >> 2;
            const int c2 = (lane & 3) * 2;
            const int ja = j0 + rg, jb = j0 + rg + 8;
            const float* Ap  = g_A  + (size_t)p * C_;
            const float* Ccp = g_Cc + (size_t)b * C_;
            const float* Dp  = g_D  + (size_t)p * C_;
            const float* Ep  = g_Ec + (size_t)b * C_;
            const float* Bva = g_Bv + ((size_t)(b * N_ + ja)) * C_;
            const float* Bvb = g_Bv + ((size_t)(b * N_ + jb)) * C_;
            float* outa = out + ((size_t)p * N_ + ja) * C_;
            float* outb = out + ((size_t)p * N_ + jb) * C_;
            const bool da = (ja == i), db = (jb == i);
#pragma unroll
            for (int nt = 0; nt < 8; nt++) {
                const int o = nh * 64 + nt * 8 + c2;
                float2 av = *reinterpret_cast<const float2*>(Ap + o);
                float2 cv = *reinterpret_cast<const float2*>(Ccp + o);
                const float addx = av.x + cv.x, addy = av.y + cv.y;
                float2 dd, ee;
                if (da || db) {
                    dd = *reinterpret_cast<const float2*>(Dp + o);
                    ee = *reinterpret_cast<const float2*>(Ep + o);
                }
                {
                    float2 bv = *reinterpret_cast<const float2*>(Bva + o);
                    float e0 = acc[nt][0] + addx + bv.x;
                    float e1 = acc[nt][1] + addy + bv.y;
                    if (da) { e0 += dd.x + ee.x; e1 += dd.y + ee.y; }
                    float2 o2; o2.x = gelu_exact(e0); o2.y = gelu_exact(e1);
                    *reinterpret_cast<float2*>(outa + o) = o2;
                }
                {
                    float2 bv = *reinterpret_cast<const float2*>(Bvb + o);
                    float e0 = acc[nt][2] + addx + bv.x;
                    float e1 = acc[nt][3] + addy + bv.y;
                    if (db) { e0 += dd.x + ee.x; e1 += dd.y + ee.y; }
                    float2 o2; o2.x = gelu_exact(e0); o2.y = gelu_exact(e1);
                    *reinterpret_cast<float2*>(outb + o) = o2;
                }
            }
        }
        CP_WAIT0();
        __syncthreads();
    }
}

} // anonymous namespace

// ---------------- launch -----------------------------------------------------
extern "C" void kernel_launch(void* const* d_in, const int* in_sizes, int n_in,
                              void* d_out, int out_size) {
    const float* x   = (const float*)d_in[0];
    const float* Wi  = (const float*)d_in[3];
    const float* bi  = (const float*)d_in[4];
    const float* lg  = (const float*)d_in[5];
    const float* lb  = (const float*)d_in[6];
    const float* c00 = (const float*)d_in[7];
    const float* c01 = (const float*)d_in[8];
    const float* c10 = (const float*)d_in[9];
    const float* c11 = (const float*)d_in[10];
    float* out = (float*)d_out;

    cudaFuncSetAttribute(k_input, cudaFuncAttributeMaxDynamicSharedMemorySize, KI_SM);
    cudaFuncSetAttribute(k_main,  cudaFuncAttributeMaxDynamicSharedMemorySize, SM_MAIN);

    k_input <<<296, 256, KI_SM>>>(x, Wi, bi, lg, lb);   // R7 exact
    k_colmix<<<376, 256>>>(c00, c01, c10, c11);         // coeffs + coalesced col/diag
    k_abd_ce<<<160, 512>>>();                           // R7 exact
    k_main  <<<148, 256, SM_MAIN>>>(out);               // R7 exact
}

// round 12
// speedup vs baseline: 1.9892x; 1.3190x over previous
#include <cuda_runtime.h>
#include <cuda_bf16.h>
#include <cuda_fp16.h>
#include <math.h>
#include <stdint.h>

namespace {

constexpr int B_ = 32;
constexpr int N_ = 64;
constexpr int C_ = 128;
constexpr int M_ = 15;
constexpr int E_ = B_ * N_ * N_;   // 131072
constexpr float LN_EPS = 1e-5f;
constexpr int TSTR = 136;          // padded 16-bit row stride (272B: conflict-free ldmatrix)
constexpr int WSEG = 128 * TSTR;   // elements per weight segment

// ---------------- device scratch --------------------------------------------
// t stored as fp16 value + bf16 residual (t = f16 + r, r accurate to 2^-20)
__device__ __align__(16) __half         g_tf16[(size_t)E_ * C_];
__device__ __align__(16) __nv_bfloat16  g_tr  [(size_t)E_ * C_];
__device__ __align__(16) float g_row [B_ * N_ * C_];
__device__ __align__(16) float g_col [B_ * N_ * C_];
__device__ __align__(16) float g_diag[B_ * N_ * C_];
__device__ __align__(16) float g_A [B_ * N_ * C_];
__device__ __align__(16) float g_Bv[B_ * N_ * C_];
__device__ __align__(16) float g_D [B_ * N_ * C_];
__device__ __align__(16) float g_Cc[B_ * C_];
__device__ __align__(16) float g_Ec[B_ * C_];
__device__ __align__(16) float g_WT[M_ * C_ * C_];        // [m][c][o]
__device__ __align__(16) __half g_Wf[2 * WSEG];           // {W0 f16, W1 f16}

// ---------------- helpers ----------------------------------------------------
__device__ __forceinline__ float gelu_exact(float v) {
    return 0.5f * v * (1.0f + erff(v * 0.70710678118654752440f));
}
__device__ __forceinline__ uint32_t smem_to_u32(const void* p) {
    uint32_t a;
    asm("{ .reg .u64 t; cvta.to.shared.u64 t, %1; cvt.u32.u64 %0, t; }" : "=r"(a) : "l"(p));
    return a;
}
__device__ __forceinline__ void ldsm4(uint32_t* r, uint32_t addr) {
    asm volatile("ldmatrix.sync.aligned.m8n8.x4.shared.b16 {%0,%1,%2,%3}, [%4];"
                 : "=r"(r[0]), "=r"(r[1]), "=r"(r[2]), "=r"(r[3]) : "r"(addr));
}
__device__ __forceinline__ void mma_bf16(float* d, const uint32_t* a,
                                         uint32_t b0, uint32_t b1) {
    asm volatile("mma.sync.aligned.m16n8k16.row.col.f32.bf16.bf16.f32 "
                 "{%0,%1,%2,%3}, {%4,%5,%6,%7}, {%8,%9}, {%0,%1,%2,%3};"
                 : "+f"(d[0]), "+f"(d[1]), "+f"(d[2]), "+f"(d[3])
                 : "r"(a[0]), "r"(a[1]), "r"(a[2]), "r"(a[3]), "r"(b0), "r"(b1));
}
__device__ __forceinline__ void mma_f16(float* d, const uint32_t* a,
                                        uint32_t b0, uint32_t b1) {
    asm volatile("mma.sync.aligned.m16n8k16.row.col.f32.f16.f16.f32 "
                 "{%0,%1,%2,%3}, {%4,%5,%6,%7}, {%8,%9}, {%0,%1,%2,%3};"
                 : "+f"(d[0]), "+f"(d[1]), "+f"(d[2]), "+f"(d[3])
                 : "r"(a[0]), "r"(a[1]), "r"(a[2]), "r"(a[3]), "r"(b0), "r"(b1));
}
__device__ __forceinline__ void cvt_split4(float4 v, uint2& h, uint2& l) {
    __nv_bfloat162 h0 = __floats2bfloat162_rn(v.x, v.y);
    __nv_bfloat162 h1 = __floats2bfloat162_rn(v.z, v.w);
    float r0 = v.x - __bfloat162float(h0.x);
    float r1 = v.y - __bfloat162float(h0.y);
    float r2 = v.z - __bfloat162float(h1.x);
    float r3 = v.w - __bfloat162float(h1.y);
    __nv_bfloat162 l0 = __floats2bfloat162_rn(r0, r1);
    __nv_bfloat162 l1 = __floats2bfloat162_rn(r2, r3);
    h.x = *reinterpret_cast<uint32_t*>(&h0); h.y = *reinterpret_cast<uint32_t*>(&h1);
    l.x = *reinterpret_cast<uint32_t*>(&l0); l.y = *reinterpret_cast<uint32_t*>(&l1);
}
// pack (a,b) as half2, residual as bf16x2
__device__ __forceinline__ uint32_t pack_f16_res(float a, float b, uint32_t& res) {
    __half2 h = __floats2half2_rn(a, b);
    float r0 = a - __half2float(__low2half(h));
    float r1 = b - __half2float(__high2half(h));
    __nv_bfloat162 l = __floats2bfloat162_rn(r0, r1);
    res = *reinterpret_cast<uint32_t*>(&l);
    return *reinterpret_cast<uint32_t*>(&h);
}

#define CP_ASYNC16(dst, src) \
    asm volatile("cp.async.cg.shared.global [%0], [%1], 16;" :: "r"(dst), "l"(src))
#define CP_COMMIT() asm volatile("cp.async.commit_group;" ::: "memory")
#define CP_WAIT0()  asm volatile("cp.async.wait_group 0;" ::: "memory")

// ---------------- K1: warp-MMA input GEMM (bf16 3-term) + GELU + LN ---------
constexpr int KI_WH = 0;
constexpr int KI_WL = 34816;
constexpr int KI_XH = 69632;
constexpr int KI_XL = 87040;
constexpr int KI_BI = 104448;
constexpr int KI_LG = 104960;
constexpr int KI_LB = 105472;
constexpr int KI_HR = 105984;
constexpr int KI_CS = 107008;
constexpr int KI_SM = 107520;

__global__ void __launch_bounds__(256) k_input(
        const float* __restrict__ x, const float* __restrict__ Wi,
        const float* __restrict__ bi, const float* __restrict__ lg,
        const float* __restrict__ lb) {
    extern __shared__ __align__(16) unsigned char smem[];
    const uint32_t sb = smem_to_u32(smem);
    const int tid = threadIdx.x, wid = tid >> 5, lane = tid & 31;
    const int j0 = (wid & 3) * 16, nh = wid >> 2;
    const int rg = lane >> 2, c2 = (lane & 3) * 2;

    for (int u = 0; u < 16; u++) {
        int idx = u * 256 + tid;
        int o = idx >> 5, c4 = (idx & 31) * 4;
        float4 v = *reinterpret_cast<const float4*>(Wi + o * C_ + c4);
        uint2 h, l; cvt_split4(v, h, l);
        uint32_t so = (uint32_t)(o * TSTR + c4) * 2;
        *reinterpret_cast<uint2*>(smem + KI_WH + so) = h;
        *reinterpret_cast<uint2*>(smem + KI_WL + so) = l;
    }
    if (tid < 128) {
        reinterpret_cast<float*>(smem + KI_BI)[tid] = bi[tid];
        reinterpret_cast<float*>(smem + KI_LG)[tid] = lg[tid];
        reinterpret_cast<float*>(smem + KI_LB)[tid] = lb[tid];
    }

    const uint32_t a_off = (uint32_t)((lane & 15) * TSTR + ((lane >> 4) << 3)) * 2;
    const uint32_t b_off = (uint32_t)((((lane >> 4) << 3) + (lane & 7)) * TSTR
                                      + (((lane >> 3) & 1) << 3)) * 2;
    const float* bi_s = reinterpret_cast<const float*>(smem + KI_BI);
    const float* lg_s = reinterpret_cast<const float*>(smem + KI_LG);
    const float* lb_s = reinterpret_cast<const float*>(smem + KI_LB);
    float* cs_s = reinterpret_cast<float*>(smem + KI_CS);
    float2* hr = reinterpret_cast<float2*>(smem + KI_HR);

    for (int p = blockIdx.x; p < B_ * N_; p += gridDim.x) {
        __syncthreads();
        if (tid < 128) cs_s[tid] = 0.f;
        {
            const float* xs = x + (size_t)p * (N_ * C_);
            for (int u = 0; u < 8; u++) {
                int idx = u * 256 + tid;
                int r = idx >> 5, c4 = (idx & 31) * 4;
                float4 v = *reinterpret_cast<const float4*>(xs + r * C_ + c4);
                uint2 h, l; cvt_split4(v, h, l);
                uint32_t so = (uint32_t)(r * TSTR + c4) * 2;
                *reinterpret_cast<uint2*>(smem + KI_XH + so) = h;
                *reinterpret_cast<uint2*>(smem + KI_XL + so) = l;
            }
        }
        __syncthreads();

        float acc[8][4];
#pragma unroll
        for (int nt = 0; nt < 8; nt++)
#pragma unroll
            for (int q = 0; q < 4; q++) acc[nt][q] = 0.f;

#pragma unroll 1
        for (int kt = 0; kt < 8; kt++) {
            const uint32_t kb = kt * 32;
            const uint32_t arow = (uint32_t)(j0 * TSTR) * 2 + a_off + kb;
            uint32_t xh[4], xl[4];
            ldsm4(xh, sb + KI_XH + arow);
            ldsm4(xl, sb + KI_XL + arow);
#pragma unroll
            for (int np = 0; np < 4; np++) {
                const uint32_t brow =
                    (uint32_t)((nh * 64 + np * 16) * TSTR) * 2 + b_off + kb;
                uint32_t wh[4], wl[4];
                ldsm4(wh, sb + KI_WH + brow);
                ldsm4(wl, sb + KI_WL + brow);
#pragma unroll
                for (int e = 0; e < 2; e++) {
                    float* d = acc[np * 2 + e];
                    const int rgi = e * 2;
                    mma_bf16(d, xh, wh[rgi], wh[rgi + 1]);
                    mma_bf16(d, xh, wl[rgi], wl[rgi + 1]);
                    mma_bf16(d, xl, wh[rgi], wh[rgi + 1]);
                }
            }
        }

        // ---- epilogue: bias + GELU, LN stats ----
        float sa = 0.f, ssa = 0.f, sbm = 0.f, ssb = 0.f;
#pragma unroll
        for (int nt = 0; nt < 8; nt++) {
            const int o = nh * 64 + nt * 8 + c2;
            const float b0 = bi_s[o], b1 = bi_s[o + 1];
            acc[nt][0] = gelu_exact(acc[nt][0] + b0);
            acc[nt][1] = gelu_exact(acc[nt][1] + b1);
            acc[nt][2] = gelu_exact(acc[nt][2] + b0);
            acc[nt][3] = gelu_exact(acc[nt][3] + b1);
            sa  += acc[nt][0] + acc[nt][1];
            ssa += acc[nt][0] * acc[nt][0] + acc[nt][1] * acc[nt][1];
            sbm += acc[nt][2] + acc[nt][3];
            ssb += acc[nt][2] * acc[nt][2] + acc[nt][3] * acc[nt][3];
        }
#pragma unroll
        for (int off = 1; off <= 2; off <<= 1) {
            sa  += __shfl_xor_sync(0xffffffffu, sa,  off);
            ssa += __shfl_xor_sync(0xffffffffu, ssa, off);
            sbm += __shfl_xor_sync(0xffffffffu, sbm, off);
            ssb += __shfl_xor_sync(0xffffffffu, ssb, off);
        }
        if ((lane & 3) == 0) {
            hr[(j0 + rg) * 2 + nh]     = make_float2(sa, ssa);
            hr[(j0 + rg + 8) * 2 + nh] = make_float2(sbm, ssb);
        }
        __syncthreads();
        const int ja = j0 + rg, jb = j0 + rg + 8;
        float2 ha0 = hr[ja * 2 + 0], ha1 = hr[ja * 2 + 1];
        float2 hb0 = hr[jb * 2 + 0], hb1 = hr[jb * 2 + 1];
        const float mua = (ha0.x + ha1.x) * (1.0f / C_);
        const float inva = rsqrtf((ha0.y + ha1.y) * (1.0f / C_) - mua * mua + LN_EPS);
        const float mub = (hb0.x + hb1.x) * (1.0f / C_);
        const float invb = rsqrtf((hb0.y + hb1.y) * (1.0f / C_) - mub * mub + LN_EPS);

        uint32_t* th32 = reinterpret_cast<uint32_t*>(g_tf16);
        uint32_t* tr32 = reinterpret_cast<uint32_t*>(g_tr);
        const size_t rba = ((size_t)p * N_ + ja) * (C_ / 2);
        const size_t rbb = ((size_t)p * N_ + jb) * (C_ / 2);
#pragma unroll
        for (int nt = 0; nt < 8; nt++) {
            const int o = nh * 64 + nt * 8 + c2;
            const float g0 = lg_s[o], g1 = lg_s[o + 1];
            const float z0 = lb_s[o], z1 = lb_s[o + 1];
            float n0 = (acc[nt][0] - mua) * inva * g0 + z0;
            float n1 = (acc[nt][1] - mua) * inva * g1 + z1;
            float n2 = (acc[nt][2] - mub) * invb * g0 + z0;
            float n3 = (acc[nt][3] - mub) * invb * g1 + z1;
            uint32_t res;
            uint32_t hv = pack_f16_res(n0, n1, res);
            th32[rba + (o >> 1)] = hv; tr32[rba + (o >> 1)] = res;
            hv = pack_f16_res(n2, n3, res);
            th32[rbb + (o >> 1)] = hv; tr32[rbb + (o >> 1)] = res;
            float cs0 = n0 + n2, cs1 = n1 + n3;
#pragma unroll
            for (int off = 4; off <= 16; off <<= 1) {
                cs0 += __shfl_xor_sync(0xffffffffu, cs0, off);
                cs1 += __shfl_xor_sync(0xffffffffu, cs1, off);
            }
            if (rg == 0) {
                atomicAdd(&cs_s[o], cs0);
                atomicAdd(&cs_s[o + 1], cs1);
            }
        }
        __syncthreads();
        if (tid < 128) g_row[p * C_ + tid] = cs_s[tid] * (1.0f / N_);
    }
}

// ---------------- K2: coeffs (+ fp16 W0/W1) + coalesced col means + diag ----
__global__ void __launch_bounds__(256) k_colmix(
        const float* __restrict__ c00, const float* __restrict__ c01,
        const float* __restrict__ c10, const float* __restrict__ c11) {
    const int bx = blockIdx.x, tid = threadIdx.x;
    if (bx < 120) {
#pragma unroll
        for (int u = 0; u < 8; u++) {
            int idx = bx * 2048 + u * 256 + tid;
            int o = idx & 127, c = (idx >> 7) & 127, m = idx >> 14;
            float v = c00[o * M_ + m] * c10[o * C_ + c] + c01[c * M_ + m] * c11[o * C_ + c];
            g_WT[idx] = v;
            if (m < 2) g_Wf[m * WSEG + o * TSTR + c] = __float2half_rn(v);
        }
    } else {
        const int cb = bx - 120;              // 0..255
        const int b = cb >> 3, qg = cb & 7;
        const int ql = tid >> 5, lane = tid & 31;
        const int q = qg * 8 + ql;
        const int c0 = lane * 4;
        const uint2* th = reinterpret_cast<const uint2*>(g_tf16);
        const uint2* tr = reinterpret_cast<const uint2*>(g_tr);
        const size_t base = ((size_t)(b * N_) * N_ + q) * (C_ / 4) + (c0 >> 2);
        const size_t istep = (size_t)N_ * (C_ / 4);
        float s0 = 0.f, s1 = 0.f, s2 = 0.f, s3 = 0.f;
        float d0 = 0.f, d1 = 0.f, d2 = 0.f, d3 = 0.f;
#pragma unroll 4
        for (int i = 0; i < N_; i++) {
            uint2 hv = th[base + (size_t)i * istep];
            uint2 rv = tr[base + (size_t)i * istep];
            __half2 h0 = *reinterpret_cast<__half2*>(&hv.x);
            __half2 h1 = *reinterpret_cast<__half2*>(&hv.y);
            __nv_bfloat162 r0 = *reinterpret_cast<__nv_bfloat162*>(&rv.x);
            __nv_bfloat162 r1 = *reinterpret_cast<__nv_bfloat162*>(&rv.y);
            float v0 = __half2float(__low2half(h0))  + __bfloat162float(r0.x);
            float v1 = __half2float(__high2half(h0)) + __bfloat162float(r0.y);
            float v2 = __half2float(__low2half(h1))  + __bfloat162float(r1.x);
            float v3 = __half2float(__high2half(h1)) + __bfloat162float(r1.y);
            s0 += v0; s1 += v1; s2 += v2; s3 += v3;
            if (i == q) { d0 = v0; d1 = v1; d2 = v2; d3 = v3; }
        }
        float* cp = g_col  + (size_t)(b * N_ + q) * C_ + c0;
        float* dp = g_diag + (size_t)(b * N_ + q) * C_ + c0;
        cp[0] = s0 * (1.0f / N_); cp[1] = s1 * (1.0f / N_);
        cp[2] = s2 * (1.0f / N_); cp[3] = s3 * (1.0f / N_);
        dp[0] = d0; dp[1] = d1; dp[2] = d2; dp[3] = d3;
    }
}

// ---------------- K3: A,Bv,D + Cc,Ec ----------------------------------------
__global__ void __launch_bounds__(512) k_abd_ce() {
    const int tid = threadIdx.x;
    if (blockIdx.x < 128) {
        __shared__ float s_in[3 * 16 * C_];
        float* sd = s_in;
        float* sr = s_in + 16 * C_;
        float* sc = s_in + 32 * C_;
        const int rb = blockIdx.x * 16;
        for (int idx = tid; idx < 16 * C_; idx += 512) {
            sd[idx] = g_diag[rb * C_ + idx];
            sr[idx] = g_row [rb * C_ + idx];
            sc[idx] = g_col [rb * C_ + idx];
        }
        __syncthreads();
        const int o = tid & 127, grp = tid >> 7;
        const float* W[9] = {
            g_WT + 2 * C_ * C_, g_WT + 4 * C_ * C_, g_WT + 6 * C_ * C_,
            g_WT + 3 * C_ * C_, g_WT + 5 * C_ * C_, g_WT + 7 * C_ * C_,
            g_WT + 10 * C_ * C_, g_WT + 11 * C_ * C_, g_WT + 12 * C_ * C_
        };
        float acc[4][3];
#pragma unroll
        for (int r = 0; r < 4; r++) { acc[r][0] = acc[r][1] = acc[r][2] = 0.f; }
#pragma unroll 1
        for (int c0 = 0; c0 < C_; c0 += 4) {
            float w[4][9];
#pragma unroll
            for (int u = 0; u < 4; u++) {
                int wi = (c0 + u) * C_ + o;
#pragma unroll
                for (int m = 0; m < 9; m++) w[u][m] = W[m][wi];
            }
#pragma unroll
            for (int u = 0; u < 4; u++) {
                int c = c0 + u;
#pragma unroll
                for (int r = 0; r < 4; r++) {
                    int rr = grp * 4 + r;
                    float d = sd[rr * C_ + c], ro = sr[rr * C_ + c], co = sc[rr * C_ + c];
                    acc[r][0] = fmaf(w[u][0], d, fmaf(w[u][1], ro, fmaf(w[u][2], co, acc[r][0])));
                    acc[r][1] = fmaf(w[u][3], d, fmaf(w[u][4], ro, fmaf(w[u][5], co, acc[r][1])));
                    acc[r][2] = fmaf(w[u][6], d, fmaf(w[u][7], ro, fmaf(w[u][8], co, acc[r][2])));
                }
            }
        }
#pragma unroll
        for (int r = 0; r < 4; r++) {
            int rr = rb + grp * 4 + r;
            g_A [rr * C_ + o] = acc[r][0];
            g_Bv[rr * C_ + o] = acc[r][1];
            g_D [rr * C_ + o] = acc[r][2];
        }
    } else {
        __shared__ float str[C_], sto[C_], red[8][C_];
        const int b = blockIdx.x - 128;
        if (tid < C_) {
            float st = 0.f, so = 0.f;
#pragma unroll 4
            for (int q = 0; q < N_; q++) {
                st += g_diag[(b * N_ + q) * C_ + tid];
                so += g_row [(b * N_ + q) * C_ + tid];
            }
            str[tid] = st * (1.0f / N_);
            sto[tid] = so * (1.0f / N_);
        }
        __syncthreads();
        const int o = tid & 127, grp = tid >> 7;
        const float* W8  = g_WT + 8  * C_ * C_;
        const float* W9  = g_WT + 9  * C_ * C_;
        const float* W13 = g_WT + 13 * C_ * C_;
        const float* W14 = g_WT + 14 * C_ * C_;
        float a = 0.f, e = 0.f;
        for (int c = grp * 32; c < grp * 32 + 32; c++) {
            int wi = c * C_ + o;
            float tr = str[c], to = sto[c];
            a = fmaf(W8 [wi], tr, fmaf(W9 [wi], to, a));
            e = fmaf(W13[wi], tr, fmaf(W14[wi], to, e));
        }
        red[grp][o] = a; red[4 + grp][o] = e;
        __syncthreads();
        if (tid < C_) {
            g_Cc[b * C_ + tid] = red[0][tid] + red[1][tid] + red[2][tid] + red[3][tid];
            g_Ec[b * C_ + tid] = red[4][tid] + red[5][tid] + red[6][tid] + red[7][tid];
        }
    }
}

// ---------------- K4: fp16 warp-MMA main GEMM pair — 2 blocks/SM ------------
// smem: W0 f16 [128][136] @0 (34816), W1 @34816, T1 f16 @69632 (17408), T2 @87040
constexpr int SMB_W0 = 0;
constexpr int SMB_W1 = 34816;
constexpr int SMB_T1 = 69632;
constexpr int SMB_T2 = 87040;
constexpr int SM_MAIN = 104448;

__global__ void __launch_bounds__(256) k_main(float* __restrict__ out) {
    extern __shared__ __align__(16) unsigned char smem[];
    const uint32_t sb = smem_to_u32(smem);
    const int tid = threadIdx.x, wid = tid >> 5, lane = tid & 31;
    const int j0 = (wid & 3) * 16;
    const int nh = wid >> 2;

    {   // resident fp16 weights (prepacked layout)
        const uint4* src = reinterpret_cast<const uint4*>(g_Wf);
        uint4* dst = reinterpret_cast<uint4*>(smem);
        for (int i = tid; i < 2 * WSEG * 2 / 16; i += 256) dst[i] = src[i];
    }

    const uint32_t a_off = (uint32_t)((lane & 15) * TSTR + ((lane >> 4) << 3)) * 2;
    const uint32_t b_off = (uint32_t)((((lane >> 4) << 3) + (lane & 7)) * TSTR
                                      + (((lane >> 3) & 1) << 3)) * 2;

    auto stage = [&](int p) {   // 8 cp.async x 16B per thread (fp16 only)
        const int b = p >> 6, i = p & 63;
        const char* s1 = reinterpret_cast<const char*>(g_tf16 + (size_t)p * (N_ * C_));
#pragma unroll
        for (int u = 0; u < 4; u++) {
            int ch = u * 256 + tid;         // 0..1023
            int r = ch >> 4, c = ch & 15;
            uint32_t dso = (uint32_t)(r * TSTR + c * 8) * 2;
            CP_ASYNC16(sb + SMB_T1 + dso, s1 + ch * 16);
            const size_t r2 = ((size_t)((b * N_ + r) * N_ + i)) * C_;
            CP_ASYNC16(sb + SMB_T2 + dso, reinterpret_cast<const char*>(g_tf16 + r2) + c * 16);
        }
    };

    int p = blockIdx.x;
    if (p < B_ * N_) { stage(p); CP_COMMIT(); }
    CP_WAIT0();
    __syncthreads();

    for (; p < B_ * N_; p += gridDim.x) {
        const int b = p >> 6, i = p & 63;

        // ---- MMA mainloop (fp16 single-term) ----
        float acc[8][4];
#pragma unroll
        for (int nt = 0; nt < 8; nt++)
#pragma unroll
            for (int q = 0; q < 4; q++) acc[nt][q] = 0.f;

#pragma unroll 1
        for (int kt = 0; kt < 8; kt++) {
            const uint32_t kb = kt * 32;
            const uint32_t arow = (uint32_t)(j0 * TSTR) * 2 + a_off + kb;
            uint32_t a1[4], a2[4];
            ldsm4(a1, sb + SMB_T1 + arow);
            ldsm4(a2, sb + SMB_T2 + arow);
#pragma unroll
            for (int np = 0; np < 4; np++) {
                const uint32_t brow =
                    (uint32_t)((nh * 64 + np * 16) * TSTR) * 2 + b_off + kb;
                uint32_t w0[4], w1[4];
                ldsm4(w0, sb + SMB_W0 + brow);
                ldsm4(w1, sb + SMB_W1 + brow);
#pragma unroll
                for (int e = 0; e < 2; e++) {
                    float* d = acc[np * 2 + e];
                    const int rgi = e * 2;
                    mma_f16(d, a1, w0[rgi], w0[rgi + 1]);
                    mma_f16(d, a2, w1[rgi], w1[rgi + 1]);
                }
            }
        }
        __syncthreads();                      // all warps done reading T smem
        const int pn = p + gridDim.x;
        if (pn < B_ * N_) { stage(pn); CP_COMMIT(); }   // prefetch overlaps epilogue

        // ---- epilogue: broadcasts + GELU + store ----
        {
            const int rg = lane >> 2;
            const int c2 = (lane & 3) * 2;
            const int ja = j0 + rg, jb = j0 + rg + 8;
            const float* Ap  = g_A  + (size_t)p * C_;
            const float* Ccp = g_Cc + (size_t)b * C_;
            const float* Dp  = g_D  + (size_t)p * C_;
            const float* Ep  = g_Ec + (size_t)b * C_;
            const float* Bva = g_Bv + ((size_t)(b * N_ + ja)) * C_;
            const float* Bvb = g_Bv + ((size_t)(b * N_ + jb)) * C_;
            float* outa = out + ((size_t)p * N_ + ja) * C_;
            float* outb = out + ((size_t)p * N_ + jb) * C_;
            const bool da = (ja == i), db = (jb == i);
#pragma unroll
            for (int nt = 0; nt < 8; nt++) {
                const int o = nh * 64 + nt * 8 + c2;
                float2 av = *reinterpret_cast<const float2*>(Ap + o);
                float2 cv = *reinterpret_cast<const float2*>(Ccp + o);
                const float addx = av.x + cv.x, addy = av.y + cv.y;
                float2 dd, ee;
                if (da || db) {
                    dd = *reinterpret_cast<const float2*>(Dp + o);
                    ee = *reinterpret_cast<const float2*>(Ep + o);
                }
                {
                    float2 bv = *reinterpret_cast<const float2*>(Bva + o);
                    float e0 = acc[nt][0] + addx + bv.x;
                    float e1 = acc[nt][1] + addy + bv.y;
                    if (da) { e0 += dd.x + ee.x; e1 += dd.y + ee.y; }
                    float2 o2; o2.x = gelu_exact(e0); o2.y = gelu_exact(e1);
                    *reinterpret_cast<float2*>(outa + o) = o2;
                }
                {
                    float2 bv = *reinterpret_cast<const float2*>(Bvb + o);
                    float e0 = acc[nt][2] + addx + bv.x;
                    float e1 = acc[nt][3] + addy + bv.y;
                    if (db) { e0 += dd.x + ee.x; e1 += dd.y + ee.y; }
                    float2 o2; o2.x = gelu_exact(e0); o2.y = gelu_exact(e1);
                    *reinterpret_cast<float2*>(outb + o) = o2;
                }
            }
        }
        CP_WAIT0();
        __syncthreads();
    }
}

} // anonymous namespace

// ---------------- launch -----------------------------------------------------
extern "C" void kernel_launch(void* const* d_in, const int* in_sizes, int n_in,
                              void* d_out, int out_size) {
    const float* x   = (const float*)d_in[0];
    const float* Wi  = (const float*)d_in[3];
    const float* bi  = (const float*)d_in[4];
    const float* lg  = (const float*)d_in[5];
    const float* lb  = (const float*)d_in[6];
    const float* c00 = (const float*)d_in[7];
    const float* c01 = (const float*)d_in[8];
    const float* c10 = (const float*)d_in[9];
    const float* c11 = (const float*)d_in[10];
    float* out = (float*)d_out;

    cudaFuncSetAttribute(k_input, cudaFuncAttributeMaxDynamicSharedMemorySize, KI_SM);
    cudaFuncSetAttribute(k_main,  cudaFuncAttributeMaxDynamicSharedMemorySize, SM_MAIN);

    k_input <<<296, 256, KI_SM>>>(x, Wi, bi, lg, lb);
    k_colmix<<<376, 256>>>(c00, c01, c10, c11);
    k_abd_ce<<<160, 512>>>();
    k_main  <<<296, 256, SM_MAIN>>>(out);   // 2 blocks/SM now (102 KB smem)
}

// round 13
// speedup vs baseline: 2.3761x; 1.1945x over previous
#include <cuda_runtime.h>
#include <cuda_bf16.h>
#include <cuda_fp16.h>
#include <math.h>
#include <stdint.h>

namespace {

constexpr int B_ = 32;
constexpr int N_ = 64;
constexpr int C_ = 128;
constexpr int M_ = 15;
constexpr int E_ = B_ * N_ * N_;   // 131072
constexpr float LN_EPS = 1e-5f;
constexpr int TSTR = 136;          // padded 16-bit row stride (272B: conflict-free ldmatrix)
constexpr int WSEG = 128 * TSTR;   // elements per weight segment

// ---------------- device scratch --------------------------------------------
__device__ __align__(16) __half g_tf16[(size_t)E_ * C_];   // post-LN t, fp16
__device__ __align__(16) float g_row [B_ * N_ * C_];
__device__ __align__(16) float g_col [B_ * N_ * C_];
__device__ __align__(16) float g_diag[B_ * N_ * C_];
__device__ __align__(16) float g_A [B_ * N_ * C_];
__device__ __align__(16) float g_Bv[B_ * N_ * C_];
__device__ __align__(16) float g_D [B_ * N_ * C_];
__device__ __align__(16) float g_Cc[B_ * C_];
__device__ __align__(16) float g_Ec[B_ * C_];
__device__ __align__(16) float g_WT[M_ * C_ * C_];        // [m][c][o]
__device__ __align__(16) __half g_Wf[2 * WSEG];           // {W0 f16, W1 f16}

// ---------------- helpers ----------------------------------------------------
__device__ __forceinline__ float gelu_exact(float v) {
    return 0.5f * v * (1.0f + erff(v * 0.70710678118654752440f));
}
__device__ __forceinline__ uint32_t smem_to_u32(const void* p) {
    uint32_t a;
    asm("{ .reg .u64 t; cvta.to.shared.u64 t, %1; cvt.u32.u64 %0, t; }" : "=r"(a) : "l"(p));
    return a;
}
__device__ __forceinline__ void ldsm4(uint32_t* r, uint32_t addr) {
    asm volatile("ldmatrix.sync.aligned.m8n8.x4.shared.b16 {%0,%1,%2,%3}, [%4];"
                 : "=r"(r[0]), "=r"(r[1]), "=r"(r[2]), "=r"(r[3]) : "r"(addr));
}
__device__ __forceinline__ void mma_f16(float* d, const uint32_t* a,
                                        uint32_t b0, uint32_t b1) {
    asm volatile("mma.sync.aligned.m16n8k16.row.col.f32.f16.f16.f32 "
                 "{%0,%1,%2,%3}, {%4,%5,%6,%7}, {%8,%9}, {%0,%1,%2,%3};"
                 : "+f"(d[0]), "+f"(d[1]), "+f"(d[2]), "+f"(d[3])
                 : "r"(a[0]), "r"(a[1]), "r"(a[2]), "r"(a[3]), "r"(b0), "r"(b1));
}
__device__ __forceinline__ uint2 cvt_h4(float4 v) {
    __half2 h0 = __floats2half2_rn(v.x, v.y);
    __half2 h1 = __floats2half2_rn(v.z, v.w);
    uint2 r;
    r.x = *reinterpret_cast<uint32_t*>(&h0);
    r.y = *reinterpret_cast<uint32_t*>(&h1);
    return r;
}

#define CP_ASYNC16(dst, src) \
    asm volatile("cp.async.cg.shared.global [%0], [%1], 16;" :: "r"(dst), "l"(src))
#define CP_COMMIT() asm volatile("cp.async.commit_group;" ::: "memory")
#define CP_WAIT0()  asm volatile("cp.async.wait_group 0;" ::: "memory")

// ---------------- K1: fp16 warp-MMA input GEMM + GELU + LN + row means ------
// smem: W f16 [128][136] @0 (34816), X f16 [64][136] @34816 (17408), params.
constexpr int KI_W  = 0;
constexpr int KI_X  = 34816;
constexpr int KI_BI = 52224;
constexpr int KI_LG = 52736;
constexpr int KI_LB = 53248;
constexpr int KI_HR = 53760;   // halfred[64][2] float2 = 1024
constexpr int KI_CS = 54784;   // colsum 128 f32
constexpr int KI_SM = 55296;

__global__ void __launch_bounds__(256) k_input(
        const float* __restrict__ x, const float* __restrict__ Wi,
        const float* __restrict__ bi, const float* __restrict__ lg,
        const float* __restrict__ lb) {
    extern __shared__ __align__(16) unsigned char smem[];
    const uint32_t sb = smem_to_u32(smem);
    const int tid = threadIdx.x, wid = tid >> 5, lane = tid & 31;
    const int j0 = (wid & 3) * 16, nh = wid >> 2;
    const int rg = lane >> 2, c2 = (lane & 3) * 2;

    // stage W_in as fp16 (once per block)
    for (int u = 0; u < 16; u++) {
        int idx = u * 256 + tid;                 // 4096 quads
        int o = idx >> 5, c4 = (idx & 31) * 4;
        float4 v = *reinterpret_cast<const float4*>(Wi + o * C_ + c4);
        *reinterpret_cast<uint2*>(smem + KI_W + (uint32_t)(o * TSTR + c4) * 2) = cvt_h4(v);
    }
    if (tid < 128) {
        reinterpret_cast<float*>(smem + KI_BI)[tid] = bi[tid];
        reinterpret_cast<float*>(smem + KI_LG)[tid] = lg[tid];
        reinterpret_cast<float*>(smem + KI_LB)[tid] = lb[tid];
    }

    const uint32_t a_off = (uint32_t)((lane & 15) * TSTR + ((lane >> 4) << 3)) * 2;
    const uint32_t b_off = (uint32_t)((((lane >> 4) << 3) + (lane & 7)) * TSTR
                                      + (((lane >> 3) & 1) << 3)) * 2;
    const float* bi_s = reinterpret_cast<const float*>(smem + KI_BI);
    const float* lg_s = reinterpret_cast<const float*>(smem + KI_LG);
    const float* lb_s = reinterpret_cast<const float*>(smem + KI_LB);
    float* cs_s = reinterpret_cast<float*>(smem + KI_CS);
    float2* hr = reinterpret_cast<float2*>(smem + KI_HR);

    for (int p = blockIdx.x; p < B_ * N_; p += gridDim.x) {
        __syncthreads();
        if (tid < 128) cs_s[tid] = 0.f;
        {   // stage X as fp16
            const float* xs = x + (size_t)p * (N_ * C_);
            for (int u = 0; u < 8; u++) {
                int idx = u * 256 + tid;
                int r = idx >> 5, c4 = (idx & 31) * 4;
                float4 v = *reinterpret_cast<const float4*>(xs + r * C_ + c4);
                *reinterpret_cast<uint2*>(smem + KI_X + (uint32_t)(r * TSTR + c4) * 2) = cvt_h4(v);
            }
        }
        __syncthreads();

        float acc[8][4];
#pragma unroll
        for (int nt = 0; nt < 8; nt++)
#pragma unroll
            for (int q = 0; q < 4; q++) acc[nt][q] = 0.f;

#pragma unroll 1
        for (int kt = 0; kt < 8; kt++) {
            const uint32_t kb = kt * 32;
            const uint32_t arow = (uint32_t)(j0 * TSTR) * 2 + a_off + kb;
            uint32_t xa[4];
            ldsm4(xa, sb + KI_X + arow);
#pragma unroll
            for (int np = 0; np < 4; np++) {
                const uint32_t brow =
                    (uint32_t)((nh * 64 + np * 16) * TSTR) * 2 + b_off + kb;
                uint32_t w[4];
                ldsm4(w, sb + KI_W + brow);
#pragma unroll
                for (int e = 0; e < 2; e++) {
                    float* d = acc[np * 2 + e];
                    const int rgi = e * 2;
                    mma_f16(d, xa, w[rgi], w[rgi + 1]);
                }
            }
        }

        // ---- epilogue: bias + GELU, LN stats ----
        float sa = 0.f, ssa = 0.f, sbm = 0.f, ssb = 0.f;
#pragma unroll
        for (int nt = 0; nt < 8; nt++) {
            const int o = nh * 64 + nt * 8 + c2;
            const float b0 = bi_s[o], b1 = bi_s[o + 1];
            acc[nt][0] = gelu_exact(acc[nt][0] + b0);
            acc[nt][1] = gelu_exact(acc[nt][1] + b1);
            acc[nt][2] = gelu_exact(acc[nt][2] + b0);
            acc[nt][3] = gelu_exact(acc[nt][3] + b1);
            sa  += acc[nt][0] + acc[nt][1];
            ssa += acc[nt][0] * acc[nt][0] + acc[nt][1] * acc[nt][1];
            sbm += acc[nt][2] + acc[nt][3];
            ssb += acc[nt][2] * acc[nt][2] + acc[nt][3] * acc[nt][3];
        }
#pragma unroll
        for (int off = 1; off <= 2; off <<= 1) {
            sa  += __shfl_xor_sync(0xffffffffu, sa,  off);
            ssa += __shfl_xor_sync(0xffffffffu, ssa, off);
            sbm += __shfl_xor_sync(0xffffffffu, sbm, off);
            ssb += __shfl_xor_sync(0xffffffffu, ssb, off);
        }
        if ((lane & 3) == 0) {
            hr[(j0 + rg) * 2 + nh]     = make_float2(sa, ssa);
            hr[(j0 + rg + 8) * 2 + nh] = make_float2(sbm, ssb);
        }
        __syncthreads();
        const int ja = j0 + rg, jb = j0 + rg + 8;
        float2 ha0 = hr[ja * 2 + 0], ha1 = hr[ja * 2 + 1];
        float2 hb0 = hr[jb * 2 + 0], hb1 = hr[jb * 2 + 1];
        const float mua = (ha0.x + ha1.x) * (1.0f / C_);
        const float inva = rsqrtf((ha0.y + ha1.y) * (1.0f / C_) - mua * mua + LN_EPS);
        const float mub = (hb0.x + hb1.x) * (1.0f / C_);
        const float invb = rsqrtf((hb0.y + hb1.y) * (1.0f / C_) - mub * mub + LN_EPS);

        uint32_t* th32 = reinterpret_cast<uint32_t*>(g_tf16);
        const size_t rba = ((size_t)p * N_ + ja) * (C_ / 2);
        const size_t rbb = ((size_t)p * N_ + jb) * (C_ / 2);
#pragma unroll
        for (int nt = 0; nt < 8; nt++) {
            const int o = nh * 64 + nt * 8 + c2;
            const float g0 = lg_s[o], g1 = lg_s[o + 1];
            const float z0 = lb_s[o], z1 = lb_s[o + 1];
            float n0 = (acc[nt][0] - mua) * inva * g0 + z0;
            float n1 = (acc[nt][1] - mua) * inva * g1 + z1;
            float n2 = (acc[nt][2] - mub) * invb * g0 + z0;
            float n3 = (acc[nt][3] - mub) * invb * g1 + z1;
            __half2 h;
            h = __floats2half2_rn(n0, n1);
            th32[rba + (o >> 1)] = *reinterpret_cast<uint32_t*>(&h);
            h = __floats2half2_rn(n2, n3);
            th32[rbb + (o >> 1)] = *reinterpret_cast<uint32_t*>(&h);
            float cs0 = n0 + n2, cs1 = n1 + n3;
#pragma unroll
            for (int off = 4; off <= 16; off <<= 1) {
                cs0 += __shfl_xor_sync(0xffffffffu, cs0, off);
                cs1 += __shfl_xor_sync(0xffffffffu, cs1, off);
            }
            if (rg == 0) {
                atomicAdd(&cs_s[o], cs0);
                atomicAdd(&cs_s[o + 1], cs1);
            }
        }
        __syncthreads();
        if (tid < 128) g_row[p * C_ + tid] = cs_s[tid] * (1.0f / N_);
    }
}

// ---------------- K2: coeffs (+ fp16 W0/W1) + coalesced col means + diag ----
__global__ void __launch_bounds__(256) k_colmix(
        const float* __restrict__ c00, const float* __restrict__ c01,
        const float* __restrict__ c10, const float* __restrict__ c11) {
    const int bx = blockIdx.x, tid = threadIdx.x;
    if (bx < 120) {
#pragma unroll
        for (int u = 0; u < 8; u++) {
            int idx = bx * 2048 + u * 256 + tid;
            int o = idx & 127, c = (idx >> 7) & 127, m = idx >> 14;
            float v = c00[o * M_ + m] * c10[o * C_ + c] + c01[c * M_ + m] * c11[o * C_ + c];
            g_WT[idx] = v;
            if (m < 2) g_Wf[m * WSEG + o * TSTR + c] = __float2half_rn(v);
        }
    } else {
        const int cb = bx - 120;              // 0..255
        const int b = cb >> 3, qg = cb & 7;
        const int ql = tid >> 5, lane = tid & 31;
        const int q = qg * 8 + ql;
        const int c0 = lane * 4;
        const uint2* th = reinterpret_cast<const uint2*>(g_tf16);
        const size_t base = ((size_t)(b * N_) * N_ + q) * (C_ / 4) + (c0 >> 2);
        const size_t istep = (size_t)N_ * (C_ / 4);
        float s0 = 0.f, s1 = 0.f, s2 = 0.f, s3 = 0.f;
        float d0 = 0.f, d1 = 0.f, d2 = 0.f, d3 = 0.f;
#pragma unroll 4
        for (int i = 0; i < N_; i++) {
            uint2 hv = th[base + (size_t)i * istep];
            __half2 h0 = *reinterpret_cast<__half2*>(&hv.x);
            __half2 h1 = *reinterpret_cast<__half2*>(&hv.y);
            float v0 = __half2float(__low2half(h0));
            float v1 = __half2float(__high2half(h0));
            float v2 = __half2float(__low2half(h1));
            float v3 = __half2float(__high2half(h1));
            s0 += v0; s1 += v1; s2 += v2; s3 += v3;
            if (i == q) { d0 = v0; d1 = v1; d2 = v2; d3 = v3; }
        }
        float* cp = g_col  + (size_t)(b * N_ + q) * C_ + c0;
        float* dp = g_diag + (size_t)(b * N_ + q) * C_ + c0;
        cp[0] = s0 * (1.0f / N_); cp[1] = s1 * (1.0f / N_);
        cp[2] = s2 * (1.0f / N_); cp[3] = s3 * (1.0f / N_);
        dp[0] = d0; dp[1] = d1; dp[2] = d2; dp[3] = d3;
    }
}

// ---------------- K3: A,Bv,D + Cc,Ec ----------------------------------------
__global__ void __launch_bounds__(512) k_abd_ce() {
    const int tid = threadIdx.x;
    if (blockIdx.x < 128) {
        __shared__ float s_in[3 * 16 * C_];
        float* sd = s_in;
        float* sr = s_in + 16 * C_;
        float* sc = s_in + 32 * C_;
        const int rb = blockIdx.x * 16;
        for (int idx = tid; idx < 16 * C_; idx += 512) {
            sd[idx] = g_diag[rb * C_ + idx];
            sr[idx] = g_row [rb * C_ + idx];
            sc[idx] = g_col [rb * C_ + idx];
        }
        __syncthreads();
        const int o = tid & 127, grp = tid >> 7;
        const float* W[9] = {
            g_WT + 2 * C_ * C_, g_WT + 4 * C_ * C_, g_WT + 6 * C_ * C_,
            g_WT + 3 * C_ * C_, g_WT + 5 * C_ * C_, g_WT + 7 * C_ * C_,
            g_WT + 10 * C_ * C_, g_WT + 11 * C_ * C_, g_WT + 12 * C_ * C_
        };
        float acc[4][3];
#pragma unroll
        for (int r = 0; r < 4; r++) { acc[r][0] = acc[r][1] = acc[r][2] = 0.f; }
#pragma unroll 1
        for (int c0 = 0; c0 < C_; c0 += 4) {
            float w[4][9];
#pragma unroll
            for (int u = 0; u < 4; u++) {
                int wi = (c0 + u) * C_ + o;
#pragma unroll
                for (int m = 0; m < 9; m++) w[u][m] = W[m][wi];
            }
#pragma unroll
            for (int u = 0; u < 4; u++) {
                int c = c0 + u;
#pragma unroll
                for (int r = 0; r < 4; r++) {
                    int rr = grp * 4 + r;
                    float d = sd[rr * C_ + c], ro = sr[rr * C_ + c], co = sc[rr * C_ + c];
                    acc[r][0] = fmaf(w[u][0], d, fmaf(w[u][1], ro, fmaf(w[u][2], co, acc[r][0])));
                    acc[r][1] = fmaf(w[u][3], d, fmaf(w[u][4], ro, fmaf(w[u][5], co, acc[r][1])));
                    acc[r][2] = fmaf(w[u][6], d, fmaf(w[u][7], ro, fmaf(w[u][8], co, acc[r][2])));
                }
            }
        }
#pragma unroll
        for (int r = 0; r < 4; r++) {
            int rr = rb + grp * 4 + r;
            g_A [rr * C_ + o] = acc[r][0];
            g_Bv[rr * C_ + o] = acc[r][1];
            g_D [rr * C_ + o] = acc[r][2];
        }
    } else {
        __shared__ float str[C_], sto[C_], red[8][C_];
        const int b = blockIdx.x - 128;
        if (tid < C_) {
            float st = 0.f, so = 0.f;
#pragma unroll 4
            for (int q = 0; q < N_; q++) {
                st += g_diag[(b * N_ + q) * C_ + tid];
                so += g_row [(b * N_ + q) * C_ + tid];
            }
            str[tid] = st * (1.0f / N_);
            sto[tid] = so * (1.0f / N_);
        }
        __syncthreads();
        const int o = tid & 127, grp = tid >> 7;
        const float* W8  = g_WT + 8  * C_ * C_;
        const float* W9  = g_WT + 9  * C_ * C_;
        const float* W13 = g_WT + 13 * C_ * C_;
        const float* W14 = g_WT + 14 * C_ * C_;
        float a = 0.f, e = 0.f;
        for (int c = grp * 32; c < grp * 32 + 32; c++) {
            int wi = c * C_ + o;
            float tr = str[c], to = sto[c];
            a = fmaf(W8 [wi], tr, fmaf(W9 [wi], to, a));
            e = fmaf(W13[wi], tr, fmaf(W14[wi], to, e));
        }
        red[grp][o] = a; red[4 + grp][o] = e;
        __syncthreads();
        if (tid < C_) {
            g_Cc[b * C_ + tid] = red[0][tid] + red[1][tid] + red[2][tid] + red[3][tid];
            g_Ec[b * C_ + tid] = red[4][tid] + red[5][tid] + red[6][tid] + red[7][tid];
        }
    }
}

// ---------------- K4: fp16 warp-MMA main GEMM pair (unchanged from R12) -----
constexpr int SMB_W0 = 0;
constexpr int SMB_W1 = 34816;
constexpr int SMB_T1 = 69632;
constexpr int SMB_T2 = 87040;
constexpr int SM_MAIN = 104448;

__global__ void __launch_bounds__(256) k_main(float* __restrict__ out) {
    extern __shared__ __align__(16) unsigned char smem[];
    const uint32_t sb = smem_to_u32(smem);
    const int tid = threadIdx.x, wid = tid >> 5, lane = tid & 31;
    const int j0 = (wid & 3) * 16;
    const int nh = wid >> 2;

    {   // resident fp16 weights (prepacked layout)
        const uint4* src = reinterpret_cast<const uint4*>(g_Wf);
        uint4* dst = reinterpret_cast<uint4*>(smem);
        for (int i = tid; i < 2 * WSEG * 2 / 16; i += 256) dst[i] = src[i];
    }

    const uint32_t a_off = (uint32_t)((lane & 15) * TSTR + ((lane >> 4) << 3)) * 2;
    const uint32_t b_off = (uint32_t)((((lane >> 4) << 3) + (lane & 7)) * TSTR
                                      + (((lane >> 3) & 1) << 3)) * 2;

    auto stage = [&](int p) {
        const int b = p >> 6, i = p & 63;
        const char* s1 = reinterpret_cast<const char*>(g_tf16 + (size_t)p * (N_ * C_));
#pragma unroll
        for (int u = 0; u < 4; u++) {
            int ch = u * 256 + tid;
            int r = ch >> 4, c = ch & 15;
            uint32_t dso = (uint32_t)(r * TSTR + c * 8) * 2;
            CP_ASYNC16(sb + SMB_T1 + dso, s1 + ch * 16);
            const size_t r2 = ((size_t)((b * N_ + r) * N_ + i)) * C_;
            CP_ASYNC16(sb + SMB_T2 + dso, reinterpret_cast<const char*>(g_tf16 + r2) + c * 16);
        }
    };

    int p = blockIdx.x;
    if (p < B_ * N_) { stage(p); CP_COMMIT(); }
    CP_WAIT0();
    __syncthreads();

    for (; p < B_ * N_; p += gridDim.x) {
        const int b = p >> 6, i = p & 63;

        float acc[8][4];
#pragma unroll
        for (int nt = 0; nt < 8; nt++)
#pragma unroll
            for (int q = 0; q < 4; q++) acc[nt][q] = 0.f;

#pragma unroll 1
        for (int kt = 0; kt < 8; kt++) {
            const uint32_t kb = kt * 32;
            const uint32_t arow = (uint32_t)(j0 * TSTR) * 2 + a_off + kb;
            uint32_t a1[4], a2[4];
            ldsm4(a1, sb + SMB_T1 + arow);
            ldsm4(a2, sb + SMB_T2 + arow);
#pragma unroll
            for (int np = 0; np < 4; np++) {
                const uint32_t brow =
                    (uint32_t)((nh * 64 + np * 16) * TSTR) * 2 + b_off + kb;
                uint32_t w0[4], w1[4];
                ldsm4(w0, sb + SMB_W0 + brow);
                ldsm4(w1, sb + SMB_W1 + brow);
#pragma unroll
                for (int e = 0; e < 2; e++) {
                    float* d = acc[np * 2 + e];
                    const int rgi = e * 2;
                    mma_f16(d, a1, w0[rgi], w0[rgi + 1]);
                    mma_f16(d, a2, w1[rgi], w1[rgi + 1]);
                }
            }
        }
        __syncthreads();
        const int pn = p + gridDim.x;
        if (pn < B_ * N_) { stage(pn); CP_COMMIT(); }

        // ---- epilogue: broadcasts + GELU + store ----
        {
            const int rg = lane >> 2;
            const int c2 = (lane & 3) * 2;
            const int ja = j0 + rg, jb = j0 + rg + 8;
            const float* Ap  = g_A  + (size_t)p * C_;
            const float* Ccp = g_Cc + (size_t)b * C_;
            const float* Dp  = g_D  + (size_t)p * C_;
            const float* Ep  = g_Ec + (size_t)b * C_;
            const float* Bva = g_Bv + ((size_t)(b * N_ + ja)) * C_;
            const float* Bvb = g_Bv + ((size_t)(b * N_ + jb)) * C_;
            float* outa = out + ((size_t)p * N_ + ja) * C_;
            float* outb = out + ((size_t)p * N_ + jb) * C_;
            const bool da = (ja == i), db = (jb == i);
#pragma unroll
            for (int nt = 0; nt < 8; nt++) {
                const int o = nh * 64 + nt * 8 + c2;
                float2 av = *reinterpret_cast<const float2*>(Ap + o);
                float2 cv = *reinterpret_cast<const float2*>(Ccp + o);
                const float addx = av.x + cv.x, addy = av.y + cv.y;
                float2 dd, ee;
                if (da || db) {
                    dd = *reinterpret_cast<const float2*>(Dp + o);
                    ee = *reinterpret_cast<const float2*>(Ep + o);
                }
                {
                    float2 bv = *reinterpret_cast<const float2*>(Bva + o);
                    float e0 = acc[nt][0] + addx + bv.x;
                    float e1 = acc[nt][1] + addy + bv.y;
                    if (da) { e0 += dd.x + ee.x; e1 += dd.y + ee.y; }
                    float2 o2; o2.x = gelu_exact(e0); o2.y = gelu_exact(e1);
                    *reinterpret_cast<float2*>(outa + o) = o2;
                }
                {
                    float2 bv = *reinterpret_cast<const float2*>(Bvb + o);
                    float e0 = acc[nt][2] + addx + bv.x;
                    float e1 = acc[nt][3] + addy + bv.y;
                    if (db) { e0 += dd.x + ee.x; e1 += dd.y + ee.y; }
                    float2 o2; o2.x = gelu_exact(e0); o2.y = gelu_exact(e1);
                    *reinterpret_cast<float2*>(outb + o) = o2;
                }
            }
        }
        CP_WAIT0();
        __syncthreads();
    }
}

} // anonymous namespace

// ---------------- launch -----------------------------------------------------
extern "C" void kernel_launch(void* const* d_in, const int* in_sizes, int n_in,
                              void* d_out, int out_size) {
    const float* x   = (const float*)d_in[0];
    const float* Wi  = (const float*)d_in[3];
    const float* bi  = (const float*)d_in[4];
    const float* lg  = (const float*)d_in[5];
    const float* lb  = (const float*)d_in[6];
    const float* c00 = (const float*)d_in[7];
    const float* c01 = (const float*)d_in[8];
    const float* c10 = (const float*)d_in[9];
    const float* c11 = (const float*)d_in[10];
    float* out = (float*)d_out;

    cudaFuncSetAttribute(k_input, cudaFuncAttributeMaxDynamicSharedMemorySize, KI_SM);
    cudaFuncSetAttribute(k_main,  cudaFuncAttributeMaxDynamicSharedMemorySize, SM_MAIN);

    k_input <<<592, 256, KI_SM>>>(x, Wi, bi, lg, lb);   // 4 blocks/SM, fp16 MMA
    k_colmix<<<376, 256>>>(c00, c01, c10, c11);         // coeffs + col/diag (fp16 reads)
    k_abd_ce<<<160, 512>>>();
    k_main  <<<296, 256, SM_MAIN>>>(out);               // 2 blocks/SM (unchanged)
}

// round 14
// speedup vs baseline: 2.3876x; 1.0048x over previous
#include <cuda_runtime.h>
#include <cuda_bf16.h>
#include <cuda_fp16.h>
#include <math.h>
#include <stdint.h>

namespace {

constexpr int B_ = 32;
constexpr int N_ = 64;
constexpr int C_ = 128;
constexpr int M_ = 15;
constexpr int E_ = B_ * N_ * N_;   // 131072
constexpr float LN_EPS = 1e-5f;
constexpr int TSTR = 136;          // padded 16-bit row stride (272B: conflict-free ldmatrix)
constexpr int WSEG = 128 * TSTR;   // elements per weight segment

// ---------------- device scratch --------------------------------------------
__device__ __align__(16) __half g_tf16[(size_t)E_ * C_];   // post-LN t, fp16
__device__ __align__(16) float g_row [B_ * N_ * C_];
__device__ __align__(16) float g_col [B_ * N_ * C_];
__device__ __align__(16) float g_diag[B_ * N_ * C_];
__device__ __align__(16) float g_A [B_ * N_ * C_];
__device__ __align__(16) float g_Bv[B_ * N_ * C_];
__device__ __align__(16) float g_D [B_ * N_ * C_];
__device__ __align__(16) float g_Cc[B_ * C_];
__device__ __align__(16) float g_Ec[B_ * C_];
__device__ __align__(16) float g_WT[M_ * C_ * C_];        // [m][c][o]
__device__ __align__(16) __half g_Wf[2 * WSEG];           // {W0 f16, W1 f16}

// ---------------- helpers ----------------------------------------------------
__device__ __forceinline__ float gelu_exact(float v) {
    return 0.5f * v * (1.0f + erff(v * 0.70710678118654752440f));
}
__device__ __forceinline__ uint32_t smem_to_u32(const void* p) {
    uint32_t a;
    asm("{ .reg .u64 t; cvta.to.shared.u64 t, %1; cvt.u32.u64 %0, t; }" : "=r"(a) : "l"(p));
    return a;
}
__device__ __forceinline__ void ldsm4(uint32_t* r, uint32_t addr) {
    asm volatile("ldmatrix.sync.aligned.m8n8.x4.shared.b16 {%0,%1,%2,%3}, [%4];"
                 : "=r"(r[0]), "=r"(r[1]), "=r"(r[2]), "=r"(r[3]) : "r"(addr));
}
__device__ __forceinline__ void mma_f16(float* d, const uint32_t* a,
                                        uint32_t b0, uint32_t b1) {
    asm volatile("mma.sync.aligned.m16n8k16.row.col.f32.f16.f16.f32 "
                 "{%0,%1,%2,%3}, {%4,%5,%6,%7}, {%8,%9}, {%0,%1,%2,%3};"
                 : "+f"(d[0]), "+f"(d[1]), "+f"(d[2]), "+f"(d[3])
                 : "r"(a[0]), "r"(a[1]), "r"(a[2]), "r"(a[3]), "r"(b0), "r"(b1));
}
__device__ __forceinline__ uint2 cvt_h4(float4 v) {
    __half2 h0 = __floats2half2_rn(v.x, v.y);
    __half2 h1 = __floats2half2_rn(v.z, v.w);
    uint2 r;
    r.x = *reinterpret_cast<uint32_t*>(&h0);
    r.y = *reinterpret_cast<uint32_t*>(&h1);
    return r;
}

#define CP_ASYNC16(dst, src) \
    asm volatile("cp.async.cg.shared.global [%0], [%1], 16;" :: "r"(dst), "l"(src))
#define CP_COMMIT() asm volatile("cp.async.commit_group;" ::: "memory")
#define CP_WAIT0()  asm volatile("cp.async.wait_group 0;" ::: "memory")

// ---------------- K1: fp16 warp-MMA input GEMM + GELU + LN ------------------
// Row means moved OUT (computed in k_colmix from fp16 t) — epilogue is now
// GEMM + GELU + LN + stores only.
constexpr int KI_W  = 0;
constexpr int KI_X  = 34816;
constexpr int KI_BI = 52224;
constexpr int KI_LG = 52736;
constexpr int KI_LB = 53248;
constexpr int KI_HR = 53760;   // halfred[64][2] float2 = 1024
constexpr int KI_SM = 54784;

__global__ void __launch_bounds__(256) k_input(
        const float* __restrict__ x, const float* __restrict__ Wi,
        const float* __restrict__ bi, const float* __restrict__ lg,
        const float* __restrict__ lb) {
    extern __shared__ __align__(16) unsigned char smem[];
    const uint32_t sb = smem_to_u32(smem);
    const int tid = threadIdx.x, wid = tid >> 5, lane = tid & 31;
    const int j0 = (wid & 3) * 16, nh = wid >> 2;
    const int rg = lane >> 2, c2 = (lane & 3) * 2;

    // stage W_in as fp16 (once per block)
    for (int u = 0; u < 16; u++) {
        int idx = u * 256 + tid;                 // 4096 quads
        int o = idx >> 5, c4 = (idx & 31) * 4;
        float4 v = *reinterpret_cast<const float4*>(Wi + o * C_ + c4);
        *reinterpret_cast<uint2*>(smem + KI_W + (uint32_t)(o * TSTR + c4) * 2) = cvt_h4(v);
    }
    if (tid < 128) {
        reinterpret_cast<float*>(smem + KI_BI)[tid] = bi[tid];
        reinterpret_cast<float*>(smem + KI_LG)[tid] = lg[tid];
        reinterpret_cast<float*>(smem + KI_LB)[tid] = lb[tid];
    }

    const uint32_t a_off = (uint32_t)((lane & 15) * TSTR + ((lane >> 4) << 3)) * 2;
    const uint32_t b_off = (uint32_t)((((lane >> 4) << 3) + (lane & 7)) * TSTR
                                      + (((lane >> 3) & 1) << 3)) * 2;
    const float* bi_s = reinterpret_cast<const float*>(smem + KI_BI);
    const float* lg_s = reinterpret_cast<const float*>(smem + KI_LG);
    const float* lb_s = reinterpret_cast<const float*>(smem + KI_LB);
    float2* hr = reinterpret_cast<float2*>(smem + KI_HR);

    for (int p = blockIdx.x; p < B_ * N_; p += gridDim.x) {
        __syncthreads();
        {   // stage X as fp16
            const float* xs = x + (size_t)p * (N_ * C_);
            for (int u = 0; u < 8; u++) {
                int idx = u * 256 + tid;
                int r = idx >> 5, c4 = (idx & 31) * 4;
                float4 v = *reinterpret_cast<const float4*>(xs + r * C_ + c4);
                *reinterpret_cast<uint2*>(smem + KI_X + (uint32_t)(r * TSTR + c4) * 2) = cvt_h4(v);
            }
        }
        __syncthreads();

        float acc[8][4];
#pragma unroll
        for (int nt = 0; nt < 8; nt++)
#pragma unroll
            for (int q = 0; q < 4; q++) acc[nt][q] = 0.f;

#pragma unroll 1
        for (int kt = 0; kt < 8; kt++) {
            const uint32_t kb = kt * 32;
            const uint32_t arow = (uint32_t)(j0 * TSTR) * 2 + a_off + kb;
            uint32_t xa[4];
            ldsm4(xa, sb + KI_X + arow);
#pragma unroll
            for (int np = 0; np < 4; np++) {
                const uint32_t brow =
                    (uint32_t)((nh * 64 + np * 16) * TSTR) * 2 + b_off + kb;
                uint32_t w[4];
                ldsm4(w, sb + KI_W + brow);
#pragma unroll
                for (int e = 0; e < 2; e++) {
                    float* d = acc[np * 2 + e];
                    const int rgi = e * 2;
                    mma_f16(d, xa, w[rgi], w[rgi + 1]);
                }
            }
        }

        // ---- epilogue: bias + GELU, LN stats ----
        float sa = 0.f, ssa = 0.f, sbm = 0.f, ssb = 0.f;
#pragma unroll
        for (int nt = 0; nt < 8; nt++) {
            const int o = nh * 64 + nt * 8 + c2;
            const float b0 = bi_s[o], b1 = bi_s[o + 1];
            acc[nt][0] = gelu_exact(acc[nt][0] + b0);
            acc[nt][1] = gelu_exact(acc[nt][1] + b1);
            acc[nt][2] = gelu_exact(acc[nt][2] + b0);
            acc[nt][3] = gelu_exact(acc[nt][3] + b1);
            sa  += acc[nt][0] + acc[nt][1];
            ssa += acc[nt][0] * acc[nt][0] + acc[nt][1] * acc[nt][1];
            sbm += acc[nt][2] + acc[nt][3];
            ssb += acc[nt][2] * acc[nt][2] + acc[nt][3] * acc[nt][3];
        }
#pragma unroll
        for (int off = 1; off <= 2; off <<= 1) {
            sa  += __shfl_xor_sync(0xffffffffu, sa,  off);
            ssa += __shfl_xor_sync(0xffffffffu, ssa, off);
            sbm += __shfl_xor_sync(0xffffffffu, sbm, off);
            ssb += __shfl_xor_sync(0xffffffffu, ssb, off);
        }
        if ((lane & 3) == 0) {
            hr[(j0 + rg) * 2 + nh]     = make_float2(sa, ssa);
            hr[(j0 + rg + 8) * 2 + nh] = make_float2(sbm, ssb);
        }
        __syncthreads();
        const int ja = j0 + rg, jb = j0 + rg + 8;
        float2 ha0 = hr[ja * 2 + 0], ha1 = hr[ja * 2 + 1];
        float2 hb0 = hr[jb * 2 + 0], hb1 = hr[jb * 2 + 1];
        const float mua = (ha0.x + ha1.x) * (1.0f / C_);
        const float inva = rsqrtf((ha0.y + ha1.y) * (1.0f / C_) - mua * mua + LN_EPS);
        const float mub = (hb0.x + hb1.x) * (1.0f / C_);
        const float invb = rsqrtf((hb0.y + hb1.y) * (1.0f / C_) - mub * mub + LN_EPS);

        uint32_t* th32 = reinterpret_cast<uint32_t*>(g_tf16);
        const size_t rba = ((size_t)p * N_ + ja) * (C_ / 2);
        const size_t rbb = ((size_t)p * N_ + jb) * (C_ / 2);
#pragma unroll
        for (int nt = 0; nt < 8; nt++) {
            const int o = nh * 64 + nt * 8 + c2;
            const float g0 = lg_s[o], g1 = lg_s[o + 1];
            const float z0 = lb_s[o], z1 = lb_s[o + 1];
            float n0 = (acc[nt][0] - mua) * inva * g0 + z0;
            float n1 = (acc[nt][1] - mua) * inva * g1 + z1;
            float n2 = (acc[nt][2] - mub) * invb * g0 + z0;
            float n3 = (acc[nt][3] - mub) * invb * g1 + z1;
            __half2 h;
            h = __floats2half2_rn(n0, n1);
            th32[rba + (o >> 1)] = *reinterpret_cast<uint32_t*>(&h);
            h = __floats2half2_rn(n2, n3);
            th32[rbb + (o >> 1)] = *reinterpret_cast<uint32_t*>(&h);
        }
    }
}

// ---------------- K2: coeffs + col means/diag + row means (all from fp16 t) -
// bx <  120: coefficient build.
// bx in [120,376): col means + diag (block = (b, 8 q rows), coalesced over i).
// bx in [376,632): row means (block = 8 (b,i) tiles, contiguous 16KB each).
__global__ void __launch_bounds__(256) k_colmix(
        const float* __restrict__ c00, const float* __restrict__ c01,
        const float* __restrict__ c10, const float* __restrict__ c11) {
    const int bx = blockIdx.x, tid = threadIdx.x;
    if (bx < 120) {
#pragma unroll
        for (int u = 0; u < 8; u++) {
            int idx = bx * 2048 + u * 256 + tid;
            int o = idx & 127, c = (idx >> 7) & 127, m = idx >> 14;
            float v = c00[o * M_ + m] * c10[o * C_ + c] + c01[c * M_ + m] * c11[o * C_ + c];
            g_WT[idx] = v;
            if (m < 2) g_Wf[m * WSEG + o * TSTR + c] = __float2half_rn(v);
        }
    } else if (bx < 376) {
        const int cb = bx - 120;              // 0..255
        const int b = cb >> 3, qg = cb & 7;
        const int ql = tid >> 5, lane = tid & 31;
        const int q = qg * 8 + ql;
        const int c0 = lane * 4;
        const uint2* th = reinterpret_cast<const uint2*>(g_tf16);
        const size_t base = ((size_t)(b * N_) * N_ + q) * (C_ / 4) + (c0 >> 2);
        const size_t istep = (size_t)N_ * (C_ / 4);
        float s0 = 0.f, s1 = 0.f, s2 = 0.f, s3 = 0.f;
        float d0 = 0.f, d1 = 0.f, d2 = 0.f, d3 = 0.f;
#pragma unroll 4
        for (int i = 0; i < N_; i++) {
            uint2 hv = th[base + (size_t)i * istep];
            __half2 h0 = *reinterpret_cast<__half2*>(&hv.x);
            __half2 h1 = *reinterpret_cast<__half2*>(&hv.y);
            float v0 = __half2float(__low2half(h0));
            float v1 = __half2float(__high2half(h0));
            float v2 = __half2float(__low2half(h1));
            float v3 = __half2float(__high2half(h1));
            s0 += v0; s1 += v1; s2 += v2; s3 += v3;
            if (i == q) { d0 = v0; d1 = v1; d2 = v2; d3 = v3; }
        }
        float* cp = g_col  + (size_t)(b * N_ + q) * C_ + c0;
        float* dp = g_diag + (size_t)(b * N_ + q) * C_ + c0;
        cp[0] = s0 * (1.0f / N_); cp[1] = s1 * (1.0f / N_);
        cp[2] = s2 * (1.0f / N_); cp[3] = s3 * (1.0f / N_);
        dp[0] = d0; dp[1] = d1; dp[2] = d2; dp[3] = d3;
    } else {
        __shared__ float rsum[4][C_];
        const int rb2 = bx - 376;             // 0..255, 8 (b,i) tiles each
        const int g = tid >> 6;               // 4 row groups of 16 j
        const int cp2 = tid & 63;             // half2 channel-pair index
#pragma unroll 1
        for (int u = 0; u < 8; u++) {
            const int p = rb2 * 8 + u;        // (b*64 + i)
            const uint32_t* tp =
                reinterpret_cast<const uint32_t*>(g_tf16 + (size_t)p * (N_ * C_));
            float s0 = 0.f, s1 = 0.f;
#pragma unroll 4
            for (int jr = 0; jr < 16; jr++) {
                uint32_t hv = tp[(g * 16 + jr) * (C_ / 2) + cp2];
                __half2 h = *reinterpret_cast<__half2*>(&hv);
                s0 += __half2float(__low2half(h));
                s1 += __half2float(__high2half(h));
            }
            rsum[g][cp2 * 2] = s0; rsum[g][cp2 * 2 + 1] = s1;
            __syncthreads();
            if (tid < C_)
                g_row[p * C_ + tid] =
                    (rsum[0][tid] + rsum[1][tid] + rsum[2][tid] + rsum[3][tid]) * (1.0f / N_);
            __syncthreads();
        }
    }
}

// ---------------- K3: A,Bv,D + Cc,Ec ----------------------------------------
__global__ void __launch_bounds__(512) k_abd_ce() {
    const int tid = threadIdx.x;
    if (blockIdx.x < 128) {
        __shared__ float s_in[3 * 16 * C_];
        float* sd = s_in;
        float* sr = s_in + 16 * C_;
        float* sc = s_in + 32 * C_;
        const int rb = blockIdx.x * 16;
        for (int idx = tid; idx < 16 * C_; idx += 512) {
            sd[idx] = g_diag[rb * C_ + idx];
            sr[idx] = g_row [rb * C_ + idx];
            sc[idx] = g_col [rb * C_ + idx];
        }
        __syncthreads();
        const int o = tid & 127, grp = tid >> 7;
        const float* W[9] = {
            g_WT + 2 * C_ * C_, g_WT + 4 * C_ * C_, g_WT + 6 * C_ * C_,
            g_WT + 3 * C_ * C_, g_WT + 5 * C_ * C_, g_WT + 7 * C_ * C_,
            g_WT + 10 * C_ * C_, g_WT + 11 * C_ * C_, g_WT + 12 * C_ * C_
        };
        float acc[4][3];
#pragma unroll
        for (int r = 0; r < 4; r++) { acc[r][0] = acc[r][1] = acc[r][2] = 0.f; }
#pragma unroll 1
        for (int c0 = 0; c0 < C_; c0 += 4) {
            float w[4][9];
#pragma unroll
            for (int u = 0; u < 4; u++) {
                int wi = (c0 + u) * C_ + o;
#pragma unroll
                for (int m = 0; m < 9; m++) w[u][m] = W[m][wi];
            }
#pragma unroll
            for (int u = 0; u < 4; u++) {
                int c = c0 + u;
#pragma unroll
                for (int r = 0; r < 4; r++) {
                    int rr = grp * 4 + r;
                    float d = sd[rr * C_ + c], ro = sr[rr * C_ + c], co = sc[rr * C_ + c];
                    acc[r][0] = fmaf(w[u][0], d, fmaf(w[u][1], ro, fmaf(w[u][2], co, acc[r][0])));
                    acc[r][1] = fmaf(w[u][3], d, fmaf(w[u][4], ro, fmaf(w[u][5], co, acc[r][1])));
                    acc[r][2] = fmaf(w[u][6], d, fmaf(w[u][7], ro, fmaf(w[u][8], co, acc[r][2])));
                }
            }
        }
#pragma unroll
        for (int r = 0; r < 4; r++) {
            int rr = rb + grp * 4 + r;
            g_A [rr * C_ + o] = acc[r][0];
            g_Bv[rr * C_ + o] = acc[r][1];
            g_D [rr * C_ + o] = acc[r][2];
        }
    } else {
        __shared__ float str[C_], sto[C_], red[8][C_];
        const int b = blockIdx.x - 128;
        if (tid < C_) {
            float st = 0.f, so = 0.f;
#pragma unroll 4
            for (int q = 0; q < N_; q++) {
                st += g_diag[(b * N_ + q) * C_ + tid];
                so += g_row [(b * N_ + q) * C_ + tid];
            }
            str[tid] = st * (1.0f / N_);
            sto[tid] = so * (1.0f / N_);
        }
        __syncthreads();
        const int o = tid & 127, grp = tid >> 7;
        const float* W8  = g_WT + 8  * C_ * C_;
        const float* W9  = g_WT + 9  * C_ * C_;
        const float* W13 = g_WT + 13 * C_ * C_;
        const float* W14 = g_WT + 14 * C_ * C_;
        float a = 0.f, e = 0.f;
        for (int c = grp * 32; c < grp * 32 + 32; c++) {
            int wi = c * C_ + o;
            float tr = str[c], to = sto[c];
            a = fmaf(W8 [wi], tr, fmaf(W9 [wi], to, a));
            e = fmaf(W13[wi], tr, fmaf(W14[wi], to, e));
        }
        red[grp][o] = a; red[4 + grp][o] = e;
        __syncthreads();
        if (tid < C_) {
            g_Cc[b * C_ + tid] = red[0][tid] + red[1][tid] + red[2][tid] + red[3][tid];
            g_Ec[b * C_ + tid] = red[4][tid] + red[5][tid] + red[6][tid] + red[7][tid];
        }
    }
}

// ---------------- K4: fp16 warp-MMA main GEMM pair (unchanged) --------------
constexpr int SMB_W0 = 0;
constexpr int SMB_W1 = 34816;
constexpr int SMB_T1 = 69632;
constexpr int SMB_T2 = 87040;
constexpr int SM_MAIN = 104448;

__global__ void __launch_bounds__(256) k_main(float* __restrict__ out) {
    extern __shared__ __align__(16) unsigned char smem[];
    const uint32_t sb = smem_to_u32(smem);
    const int tid = threadIdx.x, wid = tid >> 5, lane = tid & 31;
    const int j0 = (wid & 3) * 16;
    const int nh = wid >> 2;

    {   // resident fp16 weights (prepacked layout)
        const uint4* src = reinterpret_cast<const uint4*>(g_Wf);
        uint4* dst = reinterpret_cast<uint4*>(smem);
        for (int i = tid; i < 2 * WSEG * 2 / 16; i += 256) dst[i] = src[i];
    }

    const uint32_t a_off = (uint32_t)((lane & 15) * TSTR + ((lane >> 4) << 3)) * 2;
    const uint32_t b_off = (uint32_t)((((lane >> 4) << 3) + (lane & 7)) * TSTR
                                      + (((lane >> 3) & 1) << 3)) * 2;

    auto stage = [&](int p) {
        const int b = p >> 6, i = p & 63;
        const char* s1 = reinterpret_cast<const char*>(g_tf16 + (size_t)p * (N_ * C_));
#pragma unroll
        for (int u = 0; u < 4; u++) {
            int ch = u * 256 + tid;
            int r = ch >> 4, c = ch & 15;
            uint32_t dso = (uint32_t)(r * TSTR + c * 8) * 2;
            CP_ASYNC16(sb + SMB_T1 + dso, s1 + ch * 16);
            const size_t r2 = ((size_t)((b * N_ + r) * N_ + i)) * C_;
            CP_ASYNC16(sb + SMB_T2 + dso, reinterpret_cast<const char*>(g_tf16 + r2) + c * 16);
        }
    };

    int p = blockIdx.x;
    if (p < B_ * N_) { stage(p); CP_COMMIT(); }
    CP_WAIT0();
    __syncthreads();

    for (; p < B_ * N_; p += gridDim.x) {
        const int b = p >> 6, i = p & 63;

        float acc[8][4];
#pragma unroll
        for (int nt = 0; nt < 8; nt++)
#pragma unroll
            for (int q = 0; q < 4; q++) acc[nt][q] = 0.f;

#pragma unroll 1
        for (int kt = 0; kt < 8; kt++) {
            const uint32_t kb = kt * 32;
            const uint32_t arow = (uint32_t)(j0 * TSTR) * 2 + a_off + kb;
            uint32_t a1[4], a2[4];
            ldsm4(a1, sb + SMB_T1 + arow);
            ldsm4(a2, sb + SMB_T2 + arow);
#pragma unroll
            for (int np = 0; np < 4; np++) {
                const uint32_t brow =
                    (uint32_t)((nh * 64 + np * 16) * TSTR) * 2 + b_off + kb;
                uint32_t w0[4], w1[4];
                ldsm4(w0, sb + SMB_W0 + brow);
                ldsm4(w1, sb + SMB_W1 + brow);
#pragma unroll
                for (int e = 0; e < 2; e++) {
                    float* d = acc[np * 2 + e];
                    const int rgi = e * 2;
                    mma_f16(d, a1, w0[rgi], w0[rgi + 1]);
                    mma_f16(d, a2, w1[rgi], w1[rgi + 1]);
                }
            }
        }
        __syncthreads();
        const int pn = p + gridDim.x;
        if (pn < B_ * N_) { stage(pn); CP_COMMIT(); }

        // ---- epilogue: broadcasts + GELU + store ----
        {
            const int rg = lane >> 2;
            const int c2 = (lane & 3) * 2;
            const int ja = j0 + rg, jb = j0 + rg + 8;
            const float* Ap  = g_A  + (size_t)p * C_;
            const float* Ccp = g_Cc + (size_t)b * C_;
            const float* Dp  = g_D  + (size_t)p * C_;
            const float* Ep  = g_Ec + (size_t)b * C_;
            const float* Bva = g_Bv + ((size_t)(b * N_ + ja)) * C_;
            const float* Bvb = g_Bv + ((size_t)(b * N_ + jb)) * C_;
            float* outa = out + ((size_t)p * N_ + ja) * C_;
            float* outb = out + ((size_t)p * N_ + jb) * C_;
            const bool da = (ja == i), db = (jb == i);
#pragma unroll
            for (int nt = 0; nt < 8; nt++) {
                const int o = nh * 64 + nt * 8 + c2;
                float2 av = *reinterpret_cast<const float2*>(Ap + o);
                float2 cv = *reinterpret_cast<const float2*>(Ccp + o);
                const float addx = av.x + cv.x, addy = av.y + cv.y;
                float2 dd, ee;
                if (da || db) {
                    dd = *reinterpret_cast<const float2*>(Dp + o);
                    ee = *reinterpret_cast<const float2*>(Ep + o);
                }
                {
                    float2 bv = *reinterpret_cast<const float2*>(Bva + o);
                    float e0 = acc[nt][0] + addx + bv.x;
                    float e1 = acc[nt][1] + addy + bv.y;
                    if (da) { e0 += dd.x + ee.x; e1 += dd.y + ee.y; }
                    float2 o2; o2.x = gelu_exact(e0); o2.y = gelu_exact(e1);
                    *reinterpret_cast<float2*>(outa + o) = o2;
                }
                {
                    float2 bv = *reinterpret_cast<const float2*>(Bvb + o);
                    float e0 = acc[nt][2] + addx + bv.x;
                    float e1 = acc[nt][3] + addy + bv.y;
                    if (db) { e0 += dd.x + ee.x; e1 += dd.y + ee.y; }
                    float2 o2; o2.x = gelu_exact(e0); o2.y = gelu_exact(e1);
                    *reinterpret_cast<float2*>(outb + o) = o2;
                }
            }
        }
        CP_WAIT0();
        __syncthreads();
    }
}

} // anonymous namespace

// ---------------- launch -----------------------------------------------------
extern "C" void kernel_launch(void* const* d_in, const int* in_sizes, int n_in,
                              void* d_out, int out_size) {
    const float* x   = (const float*)d_in[0];
    const float* Wi  = (const float*)d_in[3];
    const float* bi  = (const float*)d_in[4];
    const float* lg  = (const float*)d_in[5];
    const float* lb  = (const float*)d_in[6];
    const float* c00 = (const float*)d_in[7];
    const float* c01 = (const float*)d_in[8];
    const float* c10 = (const float*)d_in[9];
    const float* c11 = (const float*)d_in[10];
    float* out = (float*)d_out;

    cudaFuncSetAttribute(k_input, cudaFuncAttributeMaxDynamicSharedMemorySize, KI_SM);
    cudaFuncSetAttribute(k_main,  cudaFuncAttributeMaxDynamicSharedMemorySize, SM_MAIN);

    k_input <<<592, 256, KI_SM>>>(x, Wi, bi, lg, lb);   // 4 blocks/SM, lean epilogue
    k_colmix<<<632, 256>>>(c00, c01, c10, c11);         // coeffs + col/diag + row
    k_abd_ce<<<160, 512>>>();
    k_main  <<<296, 256, SM_MAIN>>>(out);               // unchanged optimum
}

// round 15
// speedup vs baseline: 2.4212x; 1.0141x over previous
#include <cuda_runtime.h>
#include <cuda_bf16.h>
#include <cuda_fp16.h>
#include <math.h>
#include <stdint.h>

namespace {

constexpr int B_ = 32;
constexpr int N_ = 64;
constexpr int C_ = 128;
constexpr int M_ = 15;
constexpr int E_ = B_ * N_ * N_;   // 131072
constexpr float LN_EPS = 1e-5f;
constexpr int TSTR = 136;          // padded 16-bit row stride (272B: conflict-free ldmatrix)
constexpr int WSEG = 128 * TSTR;   // elements per weight segment

// ---------------- device scratch --------------------------------------------
__device__ __align__(16) __half g_tf16[(size_t)E_ * C_];   // post-LN t, fp16
__device__ __align__(16) float g_row [B_ * N_ * C_];
__device__ __align__(16) float g_col [B_ * N_ * C_];
__device__ __align__(16) float g_diag[B_ * N_ * C_];
__device__ __align__(16) float g_A [B_ * N_ * C_];
__device__ __align__(16) float g_Bv[B_ * N_ * C_];
__device__ __align__(16) float g_D [B_ * N_ * C_];
__device__ __align__(16) float g_Cc[B_ * C_];
__device__ __align__(16) float g_Ec[B_ * C_];
__device__ __align__(16) float g_WT[M_ * C_ * C_];        // [m][c][o]
__device__ __align__(16) __half g_Wf[2 * WSEG];           // {W0 f16, W1 f16}

// ---------------- helpers ----------------------------------------------------
__device__ __forceinline__ float gelu_exact(float v) {
    return 0.5f * v * (1.0f + erff(v * 0.70710678118654752440f));
}
__device__ __forceinline__ uint32_t smem_to_u32(const void* p) {
    uint32_t a;
    asm("{ .reg .u64 t; cvta.to.shared.u64 t, %1; cvt.u32.u64 %0, t; }" : "=r"(a) : "l"(p));
    return a;
}
__device__ __forceinline__ void ldsm4(uint32_t* r, uint32_t addr) {
    asm volatile("ldmatrix.sync.aligned.m8n8.x4.shared.b16 {%0,%1,%2,%3}, [%4];"
                 : "=r"(r[0]), "=r"(r[1]), "=r"(r[2]), "=r"(r[3]) : "r"(addr));
}
__device__ __forceinline__ void mma_f16(float* d, const uint32_t* a,
                                        uint32_t b0, uint32_t b1) {
    asm volatile("mma.sync.aligned.m16n8k16.row.col.f32.f16.f16.f32 "
                 "{%0,%1,%2,%3}, {%4,%5,%6,%7}, {%8,%9}, {%0,%1,%2,%3};"
                 : "+f"(d[0]), "+f"(d[1]), "+f"(d[2]), "+f"(d[3])
                 : "r"(a[0]), "r"(a[1]), "r"(a[2]), "r"(a[3]), "r"(b0), "r"(b1));
}
__device__ __forceinline__ uint2 cvt_h4(float4 v) {
    __half2 h0 = __floats2half2_rn(v.x, v.y);
    __half2 h1 = __floats2half2_rn(v.z, v.w);
    uint2 r;
    r.x = *reinterpret_cast<uint32_t*>(&h0);
    r.y = *reinterpret_cast<uint32_t*>(&h1);
    return r;
}

#define CP_ASYNC16(dst, src) \
    asm volatile("cp.async.cg.shared.global [%0], [%1], 16;" :: "r"(dst), "l"(src))
#define CP_COMMIT() asm volatile("cp.async.commit_group;" ::: "memory")
#define CP_WAIT0()  asm volatile("cp.async.wait_group 0;" ::: "memory")

// ---------------- K1: fp16 warp-MMA input GEMM + GELU + LN (unchanged) ------
constexpr int KI_W  = 0;
constexpr int KI_X  = 34816;
constexpr int KI_BI = 52224;
constexpr int KI_LG = 52736;
constexpr int KI_LB = 53248;
constexpr int KI_HR = 53760;   // halfred[64][2] float2 = 1024
constexpr int KI_SM = 54784;

__global__ void __launch_bounds__(256) k_input(
        const float* __restrict__ x, const float* __restrict__ Wi,
        const float* __restrict__ bi, const float* __restrict__ lg,
        const float* __restrict__ lb) {
    extern __shared__ __align__(16) unsigned char smem[];
    const uint32_t sb = smem_to_u32(smem);
    const int tid = threadIdx.x, wid = tid >> 5, lane = tid & 31;
    const int j0 = (wid & 3) * 16, nh = wid >> 2;
    const int rg = lane >> 2, c2 = (lane & 3) * 2;

    for (int u = 0; u < 16; u++) {
        int idx = u * 256 + tid;
        int o = idx >> 5, c4 = (idx & 31) * 4;
        float4 v = *reinterpret_cast<const float4*>(Wi + o * C_ + c4);
        *reinterpret_cast<uint2*>(smem + KI_W + (uint32_t)(o * TSTR + c4) * 2) = cvt_h4(v);
    }
    if (tid < 128) {
        reinterpret_cast<float*>(smem + KI_BI)[tid] = bi[tid];
        reinterpret_cast<float*>(smem + KI_LG)[tid] = lg[tid];
        reinterpret_cast<float*>(smem + KI_LB)[tid] = lb[tid];
    }

    const uint32_t a_off = (uint32_t)((lane & 15) * TSTR + ((lane >> 4) << 3)) * 2;
    const uint32_t b_off = (uint32_t)((((lane >> 4) << 3) + (lane & 7)) * TSTR
                                      + (((lane >> 3) & 1) << 3)) * 2;
    const float* bi_s = reinterpret_cast<const float*>(smem + KI_BI);
    const float* lg_s = reinterpret_cast<const float*>(smem + KI_LG);
    const float* lb_s = reinterpret_cast<const float*>(smem + KI_LB);
    float2* hr = reinterpret_cast<float2*>(smem + KI_HR);

    for (int p = blockIdx.x; p < B_ * N_; p += gridDim.x) {
        __syncthreads();
        {
            const float* xs = x + (size_t)p * (N_ * C_);
            for (int u = 0; u < 8; u++) {
                int idx = u * 256 + tid;
                int r = idx >> 5, c4 = (idx & 31) * 4;
                float4 v = *reinterpret_cast<const float4*>(xs + r * C_ + c4);
                *reinterpret_cast<uint2*>(smem + KI_X + (uint32_t)(r * TSTR + c4) * 2) = cvt_h4(v);
            }
        }
        __syncthreads();

        float acc[8][4];
#pragma unroll
        for (int nt = 0; nt < 8; nt++)
#pragma unroll
            for (int q = 0; q < 4; q++) acc[nt][q] = 0.f;

#pragma unroll 1
        for (int kt = 0; kt < 8; kt++) {
            const uint32_t kb = kt * 32;
            const uint32_t arow = (uint32_t)(j0 * TSTR) * 2 + a_off + kb;
            uint32_t xa[4];
            ldsm4(xa, sb + KI_X + arow);
#pragma unroll
            for (int np = 0; np < 4; np++) {
                const uint32_t brow =
                    (uint32_t)((nh * 64 + np * 16) * TSTR) * 2 + b_off + kb;
                uint32_t w[4];
                ldsm4(w, sb + KI_W + brow);
#pragma unroll
                for (int e = 0; e < 2; e++) {
                    float* d = acc[np * 2 + e];
                    const int rgi = e * 2;
                    mma_f16(d, xa, w[rgi], w[rgi + 1]);
                }
            }
        }

        float sa = 0.f, ssa = 0.f, sbm = 0.f, ssb = 0.f;
#pragma unroll
        for (int nt = 0; nt < 8; nt++) {
            const int o = nh * 64 + nt * 8 + c2;
            const float b0 = bi_s[o], b1 = bi_s[o + 1];
            acc[nt][0] = gelu_exact(acc[nt][0] + b0);
            acc[nt][1] = gelu_exact(acc[nt][1] + b1);
            acc[nt][2] = gelu_exact(acc[nt][2] + b0);
            acc[nt][3] = gelu_exact(acc[nt][3] + b1);
            sa  += acc[nt][0] + acc[nt][1];
            ssa += acc[nt][0] * acc[nt][0] + acc[nt][1] * acc[nt][1];
            sbm += acc[nt][2] + acc[nt][3];
            ssb += acc[nt][2] * acc[nt][2] + acc[nt][3] * acc[nt][3];
        }
#pragma unroll
        for (int off = 1; off <= 2; off <<= 1) {
            sa  += __shfl_xor_sync(0xffffffffu, sa,  off);
            ssa += __shfl_xor_sync(0xffffffffu, ssa, off);
            sbm += __shfl_xor_sync(0xffffffffu, sbm, off);
            ssb += __shfl_xor_sync(0xffffffffu, ssb, off);
        }
        if ((lane & 3) == 0) {
            hr[(j0 + rg) * 2 + nh]     = make_float2(sa, ssa);
            hr[(j0 + rg + 8) * 2 + nh] = make_float2(sbm, ssb);
        }
        __syncthreads();
        const int ja = j0 + rg, jb = j0 + rg + 8;
        float2 ha0 = hr[ja * 2 + 0], ha1 = hr[ja * 2 + 1];
        float2 hb0 = hr[jb * 2 + 0], hb1 = hr[jb * 2 + 1];
        const float mua = (ha0.x + ha1.x) * (1.0f / C_);
        const float inva = rsqrtf((ha0.y + ha1.y) * (1.0f / C_) - mua * mua + LN_EPS);
        const float mub = (hb0.x + hb1.x) * (1.0f / C_);
        const float invb = rsqrtf((hb0.y + hb1.y) * (1.0f / C_) - mub * mub + LN_EPS);

        uint32_t* th32 = reinterpret_cast<uint32_t*>(g_tf16);
        const size_t rba = ((size_t)p * N_ + ja) * (C_ / 2);
        const size_t rbb = ((size_t)p * N_ + jb) * (C_ / 2);
#pragma unroll
        for (int nt = 0; nt < 8; nt++) {
            const int o = nh * 64 + nt * 8 + c2;
            const float g0 = lg_s[o], g1 = lg_s[o + 1];
            const float z0 = lb_s[o], z1 = lb_s[o + 1];
            float n0 = (acc[nt][0] - mua) * inva * g0 + z0;
            float n1 = (acc[nt][1] - mua) * inva * g1 + z1;
            float n2 = (acc[nt][2] - mub) * invb * g0 + z0;
            float n3 = (acc[nt][3] - mub) * invb * g1 + z1;
            __half2 h;
            h = __floats2half2_rn(n0, n1);
            th32[rba + (o >> 1)] = *reinterpret_cast<uint32_t*>(&h);
            h = __floats2half2_rn(n2, n3);
            th32[rbb + (o >> 1)] = *reinterpret_cast<uint32_t*>(&h);
        }
    }
}

// ---------------- K2: coeffs + col/diag + row means (unchanged) -------------
__global__ void __launch_bounds__(256) k_colmix(
        const float* __restrict__ c00, const float* __restrict__ c01,
        const float* __restrict__ c10, const float* __restrict__ c11) {
    const int bx = blockIdx.x, tid = threadIdx.x;
    if (bx < 120) {
#pragma unroll
        for (int u = 0; u < 8; u++) {
            int idx = bx * 2048 + u * 256 + tid;
            int o = idx & 127, c = (idx >> 7) & 127, m = idx >> 14;
            float v = c00[o * M_ + m] * c10[o * C_ + c] + c01[c * M_ + m] * c11[o * C_ + c];
            g_WT[idx] = v;
            if (m < 2) g_Wf[m * WSEG + o * TSTR + c] = __float2half_rn(v);
        }
    } else if (bx < 376) {
        const int cb = bx - 120;
        const int b = cb >> 3, qg = cb & 7;
        const int ql = tid >> 5, lane = tid & 31;
        const int q = qg * 8 + ql;
        const int c0 = lane * 4;
        const uint2* th = reinterpret_cast<const uint2*>(g_tf16);
        const size_t base = ((size_t)(b * N_) * N_ + q) * (C_ / 4) + (c0 >> 2);
        const size_t istep = (size_t)N_ * (C_ / 4);
        float s0 = 0.f, s1 = 0.f, s2 = 0.f, s3 = 0.f;
        float d0 = 0.f, d1 = 0.f, d2 = 0.f, d3 = 0.f;
#pragma unroll 4
        for (int i = 0; i < N_; i++) {
            uint2 hv = th[base + (size_t)i * istep];
            __half2 h0 = *reinterpret_cast<__half2*>(&hv.x);
            __half2 h1 = *reinterpret_cast<__half2*>(&hv.y);
            float v0 = __half2float(__low2half(h0));
            float v1 = __half2float(__high2half(h0));
            float v2 = __half2float(__low2half(h1));
            float v3 = __half2float(__high2half(h1));
            s0 += v0; s1 += v1; s2 += v2; s3 += v3;
            if (i == q) { d0 = v0; d1 = v1; d2 = v2; d3 = v3; }
        }
        float* cp = g_col  + (size_t)(b * N_ + q) * C_ + c0;
        float* dp = g_diag + (size_t)(b * N_ + q) * C_ + c0;
        cp[0] = s0 * (1.0f / N_); cp[1] = s1 * (1.0f / N_);
        cp[2] = s2 * (1.0f / N_); cp[3] = s3 * (1.0f / N_);
        dp[0] = d0; dp[1] = d1; dp[2] = d2; dp[3] = d3;
    } else {
        __shared__ float rsum[4][C_];
        const int rb2 = bx - 376;
        const int g = tid >> 6;
        const int cp2 = tid & 63;
#pragma unroll 1
        for (int u = 0; u < 8; u++) {
            const int p = rb2 * 8 + u;
            const uint32_t* tp =
                reinterpret_cast<const uint32_t*>(g_tf16 + (size_t)p * (N_ * C_));
            float s0 = 0.f, s1 = 0.f;
#pragma unroll 4
            for (int jr = 0; jr < 16; jr++) {
                uint32_t hv = tp[(g * 16 + jr) * (C_ / 2) + cp2];
                __half2 h = *reinterpret_cast<__half2*>(&hv);
                s0 += __half2float(__low2half(h));
                s1 += __half2float(__high2half(h));
            }
            rsum[g][cp2 * 2] = s0; rsum[g][cp2 * 2 + 1] = s1;
            __syncthreads();
            if (tid < C_)
                g_row[p * C_ + tid] =
                    (rsum[0][tid] + rsum[1][tid] + rsum[2][tid] + rsum[3][tid]) * (1.0f / N_);
            __syncthreads();
        }
    }
}

// ---------------- K3: A,Bv,D + Cc,Ec (unchanged) ----------------------------
__global__ void __launch_bounds__(512) k_abd_ce() {
    const int tid = threadIdx.x;
    if (blockIdx.x < 128) {
        __shared__ float s_in[3 * 16 * C_];
        float* sd = s_in;
        float* sr = s_in + 16 * C_;
        float* sc = s_in + 32 * C_;
        const int rb = blockIdx.x * 16;
        for (int idx = tid; idx < 16 * C_; idx += 512) {
            sd[idx] = g_diag[rb * C_ + idx];
            sr[idx] = g_row [rb * C_ + idx];
            sc[idx] = g_col [rb * C_ + idx];
        }
        __syncthreads();
        const int o = tid & 127, grp = tid >> 7;
        const float* W[9] = {
            g_WT + 2 * C_ * C_, g_WT + 4 * C_ * C_, g_WT + 6 * C_ * C_,
            g_WT + 3 * C_ * C_, g_WT + 5 * C_ * C_, g_WT + 7 * C_ * C_,
            g_WT + 10 * C_ * C_, g_WT + 11 * C_ * C_, g_WT + 12 * C_ * C_
        };
        float acc[4][3];
#pragma unroll
        for (int r = 0; r < 4; r++) { acc[r][0] = acc[r][1] = acc[r][2] = 0.f; }
#pragma unroll 1
        for (int c0 = 0; c0 < C_; c0 += 4) {
            float w[4][9];
#pragma unroll
            for (int u = 0; u < 4; u++) {
                int wi = (c0 + u) * C_ + o;
#pragma unroll
                for (int m = 0; m < 9; m++) w[u][m] = W[m][wi];
            }
#pragma unroll
            for (int u = 0; u < 4; u++) {
                int c = c0 + u;
#pragma unroll
                for (int r = 0; r < 4; r++) {
                    int rr = grp * 4 + r;
                    float d = sd[rr * C_ + c], ro = sr[rr * C_ + c], co = sc[rr * C_ + c];
                    acc[r][0] = fmaf(w[u][0], d, fmaf(w[u][1], ro, fmaf(w[u][2], co, acc[r][0])));
                    acc[r][1] = fmaf(w[u][3], d, fmaf(w[u][4], ro, fmaf(w[u][5], co, acc[r][1])));
                    acc[r][2] = fmaf(w[u][6], d, fmaf(w[u][7], ro, fmaf(w[u][8], co, acc[r][2])));
                }
            }
        }
#pragma unroll
        for (int r = 0; r < 4; r++) {
            int rr = rb + grp * 4 + r;
            g_A [rr * C_ + o] = acc[r][0];
            g_Bv[rr * C_ + o] = acc[r][1];
            g_D [rr * C_ + o] = acc[r][2];
        }
    } else {
        __shared__ float str[C_], sto[C_], red[8][C_];
        const int b = blockIdx.x - 128;
        if (tid < C_) {
            float st = 0.f, so = 0.f;
#pragma unroll 4
            for (int q = 0; q < N_; q++) {
                st += g_diag[(b * N_ + q) * C_ + tid];
                so += g_row [(b * N_ + q) * C_ + tid];
            }
            str[tid] = st * (1.0f / N_);
            sto[tid] = so * (1.0f / N_);
        }
        __syncthreads();
        const int o = tid & 127, grp = tid >> 7;
        const float* W8  = g_WT + 8  * C_ * C_;
        const float* W9  = g_WT + 9  * C_ * C_;
        const float* W13 = g_WT + 13 * C_ * C_;
        const float* W14 = g_WT + 14 * C_ * C_;
        float a = 0.f, e = 0.f;
        for (int c = grp * 32; c < grp * 32 + 32; c++) {
            int wi = c * C_ + o;
            float tr = str[c], to = sto[c];
            a = fmaf(W8 [wi], tr, fmaf(W9 [wi], to, a));
            e = fmaf(W13[wi], tr, fmaf(W14[wi], to, e));
        }
        red[grp][o] = a; red[4 + grp][o] = e;
        __syncthreads();
        if (tid < C_) {
            g_Cc[b * C_ + tid] = red[0][tid] + red[1][tid] + red[2][tid] + red[3][tid];
            g_Ec[b * C_ + tid] = red[4][tid] + red[5][tid] + red[6][tid] + red[7][tid];
        }
    }
}

// ---------------- K4: fp16 warp-MMA main GEMM — N-SPLIT, 3 blocks/SM --------
// Block handles one 64-col half of each tile: blocks [0,222) -> h=0, [222,444) -> h=1.
// smem: W0half @0 (17408), W1half @17408, T1 @34816 (17408), T2 @52224. 69632 B.
constexpr int HGRID = 222;           // blocks per half; grid = 444 = 148*3
constexpr int SMB_W0 = 0;
constexpr int SMB_W1 = 17408;
constexpr int SMB_T1 = 34816;
constexpr int SMB_T2 = 52224;
constexpr int SM_MAIN = 69632;

__global__ void __launch_bounds__(256) k_main(float* __restrict__ out) {
    extern __shared__ __align__(16) unsigned char smem[];
    const uint32_t sb = smem_to_u32(smem);
    const int tid = threadIdx.x, wid = tid >> 5, lane = tid & 31;
    const int j0 = (wid & 3) * 16;       // 16 j rows
    const int nh = wid >> 2;             // 32-col quarter within this half (0..1)
    const int h = (blockIdx.x >= HGRID) ? 1 : 0;
    const int bstart = blockIdx.x - h * HGRID;

    {   // resident half-weights: rows [h*64, h*64+64) of W0 and W1
        const uint4* s0 = reinterpret_cast<const uint4*>(
            reinterpret_cast<const char*>(g_Wf) + (size_t)h * 17408);
        const uint4* s1 = reinterpret_cast<const uint4*>(
            reinterpret_cast<const char*>(g_Wf) + 34816 + (size_t)h * 17408);
        uint4* d0 = reinterpret_cast<uint4*>(smem + SMB_W0);
        uint4* d1 = reinterpret_cast<uint4*>(smem + SMB_W1);
        for (int i = tid; i < 17408 / 16; i += 256) { d0[i] = s0[i]; d1[i] = s1[i]; }
    }

    const uint32_t a_off = (uint32_t)((lane & 15) * TSTR + ((lane >> 4) << 3)) * 2;
    const uint32_t b_off = (uint32_t)((((lane >> 4) << 3) + (lane & 7)) * TSTR
                                      + (((lane >> 3) & 1) << 3)) * 2;

    auto stage = [&](int p) {   // full T1/T2 tile via cp.async (L2-resident t)
        const int b = p >> 6, i = p & 63;
        const char* s1 = reinterpret_cast<const char*>(g_tf16 + (size_t)p * (N_ * C_));
#pragma unroll
        for (int u = 0; u < 4; u++) {
            int ch = u * 256 + tid;
            int r = ch >> 4, c = ch & 15;
            uint32_t dso = (uint32_t)(r * TSTR + c * 8) * 2;
            CP_ASYNC16(sb + SMB_T1 + dso, s1 + ch * 16);
            const size_t r2 = ((size_t)((b * N_ + r) * N_ + i)) * C_;
            CP_ASYNC16(sb + SMB_T2 + dso, reinterpret_cast<const char*>(g_tf16 + r2) + c * 16);
        }
    };

    int p = bstart;
    if (p < B_ * N_) { stage(p); CP_COMMIT(); }
    CP_WAIT0();
    __syncthreads();

    for (; p < B_ * N_; p += HGRID) {
        const int b = p >> 6, i = p & 63;

        float acc[4][4];
#pragma unroll
        for (int nt = 0; nt < 4; nt++)
#pragma unroll
            for (int q = 0; q < 4; q++) acc[nt][q] = 0.f;

#pragma unroll 1
        for (int kt = 0; kt < 8; kt++) {
            const uint32_t kb = kt * 32;
            const uint32_t arow = (uint32_t)(j0 * TSTR) * 2 + a_off + kb;
            uint32_t a1[4], a2[4];
            ldsm4(a1, sb + SMB_T1 + arow);
            ldsm4(a2, sb + SMB_T2 + arow);
#pragma unroll
            for (int np = 0; np < 2; np++) {
                const uint32_t brow =
                    (uint32_t)((nh * 32 + np * 16) * TSTR) * 2 + b_off + kb;
                uint32_t w0[4], w1[4];
                ldsm4(w0, sb + SMB_W0 + brow);
                ldsm4(w1, sb + SMB_W1 + brow);
#pragma unroll
                for (int e = 0; e < 2; e++) {
                    float* d = acc[np * 2 + e];
                    const int rgi = e * 2;
                    mma_f16(d, a1, w0[rgi], w0[rgi + 1]);
                    mma_f16(d, a2, w1[rgi], w1[rgi + 1]);
                }
            }
        }
        __syncthreads();
        const int pn = p + HGRID;
        if (pn < B_ * N_) { stage(pn); CP_COMMIT(); }

        // ---- epilogue: broadcasts + GELU + store (this half's 64 cols) ----
        {
            const int rg = lane >> 2;
            const int c2 = (lane & 3) * 2;
            const int ja = j0 + rg, jb = j0 + rg + 8;
            const int ob = h * 64;
            const float* Ap  = g_A  + (size_t)p * C_ + ob;
            const float* Ccp = g_Cc + (size_t)b * C_ + ob;
            const float* Dp  = g_D  + (size_t)p * C_ + ob;
            const float* Ep  = g_Ec + (size_t)b * C_ + ob;
            const float* Bva = g_Bv + ((size_t)(b * N_ + ja)) * C_ + ob;
            const float* Bvb = g_Bv + ((size_t)(b * N_ + jb)) * C_ + ob;
            float* outa = out + ((size_t)p * N_ + ja) * C_ + ob;
            float* outb = out + ((size_t)p * N_ + jb) * C_ + ob;
            const bool da = (ja == i), db = (jb == i);
#pragma unroll
            for (int nt = 0; nt < 4; nt++) {
                const int o = nh * 32 + nt * 8 + c2;
                float2 av = *reinterpret_cast<const float2*>(Ap + o);
                float2 cv = *reinterpret_cast<const float2*>(Ccp + o);
                const float addx = av.x + cv.x, addy = av.y + cv.y;
                float2 dd, ee;
                if (da || db) {
                    dd = *reinterpret_cast<const float2*>(Dp + o);
                    ee = *reinterpret_cast<const float2*>(Ep + o);
                }
                {
                    float2 bv = *reinterpret_cast<const float2*>(Bva + o);
                    float e0 = acc[nt][0] + addx + bv.x;
                    float e1 = acc[nt][1] + addy + bv.y;
                    if (da) { e0 += dd.x + ee.x; e1 += dd.y + ee.y; }
                    float2 o2; o2.x = gelu_exact(e0); o2.y = gelu_exact(e1);
                    *reinterpret_cast<float2*>(outa + o) = o2;
                }
                {
                    float2 bv = *reinterpret_cast<const float2*>(Bvb + o);
                    float e0 = acc[nt][2] + addx + bv.x;
                    float e1 = acc[nt][3] + addy + bv.y;
                    if (db) { e0 += dd.x + ee.x; e1 += dd.y + ee.y; }
                    float2 o2; o2.x = gelu_exact(e0); o2.y = gelu_exact(e1);
                    *reinterpret_cast<float2*>(outb + o) = o2;
                }
            }
        }
        CP_WAIT0();
        __syncthreads();
    }
}

} // anonymous namespace

// ---------------- launch -----------------------------------------------------
extern "C" void kernel_launch(void* const* d_in, const int* in_sizes, int n_in,
                              void* d_out, int out_size) {
    const float* x   = (const float*)d_in[0];
    const float* Wi  = (const float*)d_in[3];
    const float* bi  = (const float*)d_in[4];
    const float* lg  = (const float*)d_in[5];
    const float* lb  = (const float*)d_in[6];
    const float* c00 = (const float*)d_in[7];
    const float* c01 = (const float*)d_in[8];
    const float* c10 = (const float*)d_in[9];
    const float* c11 = (const float*)d_in[10];
    float* out = (float*)d_out;

    cudaFuncSetAttribute(k_input, cudaFuncAttributeMaxDynamicSharedMemorySize, KI_SM);
    cudaFuncSetAttribute(k_main,  cudaFuncAttributeMaxDynamicSharedMemorySize, SM_MAIN);

    k_input <<<592, 256, KI_SM>>>(x, Wi, bi, lg, lb);   // 4 blocks/SM, fp16 MMA
    k_colmix<<<632, 256>>>(c00, c01, c10, c11);         // coeffs + col/diag + row
    k_abd_ce<<<160, 512>>>();
    k_main  <<<2 * HGRID, 256, SM_MAIN>>>(out);         // N-split, 3 blocks/SM
}